// round 1
// baseline (speedup 1.0000x reference)
#include <cuda_runtime.h>
#include <math.h>

#define B_  2
#define L_  2048
#define E_  1024
#define H_  16
#define HD_ 64

// Scratch (no allocations allowed): qkv [B,L,3E], attn [B,L,E]
__device__ float g_qkv[B_ * L_ * 3 * E_];
__device__ float g_attn[B_ * L_ * E_];

// ---------------------------------------------------------------------------
// C[m,n] = sum_k A[m,k] * W[n,k] + bias[n]
// 128x128 tile, BK=16, 256 threads, 8x8 microtile.
// M % 128 == 0, N % 128 == 0, K % 16 == 0 (true for all our shapes).
// ---------------------------------------------------------------------------
__global__ __launch_bounds__(256) void gemm_bias(
    const float* __restrict__ A, const float* __restrict__ W,
    const float* __restrict__ bias, float* __restrict__ C,
    int M, int N, int K)
{
    __shared__ float As[128][17];   // padded
    __shared__ float Ws[16][132];   // padded, rows 16B-aligned (132 % 4 == 0)

    const int bm  = blockIdx.y * 128;
    const int bn  = blockIdx.x * 128;
    const int tid = threadIdx.x;
    const int tr  = tid >> 4;   // 0..15
    const int tc  = tid & 15;   // 0..15

    float acc[8][8];
#pragma unroll
    for (int i = 0; i < 8; i++)
#pragma unroll
        for (int j = 0; j < 8; j++) acc[i][j] = 0.f;

    for (int k0 = 0; k0 < K; k0 += 16) {
        // Load A tile: 128x16 floats = 512 float4
#pragma unroll
        for (int i = 0; i < 2; i++) {
            int v   = tid * 2 + i;
            int row = v >> 2;
            int c4  = (v & 3) * 4;
            const float4 t = *(const float4*)(A + (size_t)(bm + row) * K + k0 + c4);
            As[row][c4 + 0] = t.x; As[row][c4 + 1] = t.y;
            As[row][c4 + 2] = t.z; As[row][c4 + 3] = t.w;
        }
        // Load W tile transposed: Ws[kk][n] = W[bn+n][k0+kk]
#pragma unroll
        for (int i = 0; i < 2; i++) {
            int v  = tid * 2 + i;
            int n  = v >> 2;
            int c4 = (v & 3) * 4;
            const float4 t = *(const float4*)(W + (size_t)(bn + n) * K + k0 + c4);
            Ws[c4 + 0][n] = t.x; Ws[c4 + 1][n] = t.y;
            Ws[c4 + 2][n] = t.z; Ws[c4 + 3][n] = t.w;
        }
        __syncthreads();

#pragma unroll
        for (int kk = 0; kk < 16; kk++) {
            float a[8], b[8];
#pragma unroll
            for (int i = 0; i < 8; i++) a[i] = As[tr * 8 + i][kk];
#pragma unroll
            for (int j = 0; j < 8; j++) b[j] = Ws[kk][tc * 8 + j];
#pragma unroll
            for (int i = 0; i < 8; i++)
#pragma unroll
                for (int j = 0; j < 8; j++) acc[i][j] += a[i] * b[j];
        }
        __syncthreads();
    }

#pragma unroll
    for (int i = 0; i < 8; i++) {
        int row = bm + tr * 8 + i;
#pragma unroll
        for (int j4 = 0; j4 < 8; j4 += 4) {
            int col = bn + tc * 8 + j4;
            float4 t;
            t.x = acc[i][j4 + 0] + bias[col + 0];
            t.y = acc[i][j4 + 1] + bias[col + 1];
            t.z = acc[i][j4 + 2] + bias[col + 2];
            t.w = acc[i][j4 + 3] + bias[col + 3];
            *(float4*)(C + (size_t)row * N + col) = t;
        }
    }
}

// ---------------------------------------------------------------------------
// Flash attention (fp32): one block = (b, h, 64 q-rows). Bc = 64.
// 256 threads, 16x16 grid, 4x4 microtiles for S and O.
// smem: Qs[64][65], KP[64][65] (K tile, then reused as P), Vs[64][65],
//       red[16][68] reduction scratch.
// ---------------------------------------------------------------------------
#define QS_STRIDE 65
#define RED_STRIDE 68
#define ATTN_SMEM ((3 * 64 * QS_STRIDE + 16 * RED_STRIDE) * 4)

__global__ __launch_bounds__(256) void attention_kernel(
    const float* __restrict__ qkv, float* __restrict__ attn)
{
    extern __shared__ float sm[];
    float* Qs  = sm;                       // 64*65
    float* KP  = Qs + 64 * QS_STRIDE;      // 64*65
    float* Vs  = KP + 64 * QS_STRIDE;      // 64*65
    float* red = Vs + 64 * QS_STRIDE;      // 16*68

    const int q0  = blockIdx.x * 64;
    const int h   = blockIdx.y;
    const int b   = blockIdx.z;
    const int tid = threadIdx.x;
    const int ty  = tid >> 4;  // 0..15
    const int tx  = tid & 15;  // 0..15
    const int basecol = h * HD_;

    // Load Q tile: 64 rows x 64 cols
#pragma unroll
    for (int i = 0; i < 4; i++) {
        int v   = tid + 256 * i;
        int row = v >> 4;
        int c   = (v & 15) * 4;
        const float4 t = *(const float4*)(qkv + (size_t)(b * L_ + q0 + row) * (3 * E_) + basecol + c);
        float* dst = &Qs[row * QS_STRIDE + c];
        dst[0] = t.x; dst[1] = t.y; dst[2] = t.z; dst[3] = t.w;
    }

    float o[4][4];
    float mrow[4], lrow[4];
#pragma unroll
    for (int i = 0; i < 4; i++) {
        mrow[i] = -1e30f; lrow[i] = 0.f;
#pragma unroll
        for (int j = 0; j < 4; j++) o[i][j] = 0.f;
    }

    for (int kt = 0; kt < L_; kt += 64) {
        // Load K and V tiles
#pragma unroll
        for (int i = 0; i < 4; i++) {
            int v   = tid + 256 * i;
            int row = v >> 4;
            int c   = (v & 15) * 4;
            size_t g = (size_t)(b * L_ + kt + row) * (3 * E_) + basecol + c;
            const float4 tk = *(const float4*)(qkv + g + E_);
            const float4 tv = *(const float4*)(qkv + g + 2 * E_);
            float* dk = &KP[row * QS_STRIDE + c];
            dk[0] = tk.x; dk[1] = tk.y; dk[2] = tk.z; dk[3] = tk.w;
            float* dv = &Vs[row * QS_STRIDE + c];
            dv[0] = tv.x; dv[1] = tv.y; dv[2] = tv.z; dv[3] = tv.w;
        }
        __syncthreads();

        // S[4][4] = Q(ty rows) . K(tx cols)^T, scaled
        float s[4][4];
#pragma unroll
        for (int i = 0; i < 4; i++)
#pragma unroll
            for (int j = 0; j < 4; j++) s[i][j] = 0.f;

#pragma unroll 8
        for (int d = 0; d < 64; d++) {
            float a[4], bb[4];
#pragma unroll
            for (int i = 0; i < 4; i++) a[i]  = Qs[(ty * 4 + i) * QS_STRIDE + d];
#pragma unroll
            for (int j = 0; j < 4; j++) bb[j] = KP[(tx * 4 + j) * QS_STRIDE + d];
#pragma unroll
            for (int i = 0; i < 4; i++)
#pragma unroll
                for (int j = 0; j < 4; j++) s[i][j] += a[i] * bb[j];
        }
#pragma unroll
        for (int i = 0; i < 4; i++)
#pragma unroll
            for (int j = 0; j < 4; j++) s[i][j] *= 0.125f;  // 1/sqrt(64)

        // Row-max partials -> smem reduction across tx
#pragma unroll
        for (int i = 0; i < 4; i++) {
            float pm = s[i][0];
#pragma unroll
            for (int j = 1; j < 4; j++) pm = fmaxf(pm, s[i][j]);
            red[tx * RED_STRIDE + ty * 4 + i] = pm;
        }
        __syncthreads();   // (a) all S done, all partial maxes visible

        float newm[4], alpha[4], psum[4];
#pragma unroll
        for (int i = 0; i < 4; i++) {
            float mm = mrow[i];
#pragma unroll
            for (int t = 0; t < 16; t++) mm = fmaxf(mm, red[t * RED_STRIDE + ty * 4 + i]);
            newm[i]  = mm;
            alpha[i] = __expf(mrow[i] - mm);
        }
        // exponentiate, partial sums, write P back over K tile (K reads done at (a))
#pragma unroll
        for (int i = 0; i < 4; i++) {
            float ps = 0.f;
#pragma unroll
            for (int j = 0; j < 4; j++) {
                float p = __expf(s[i][j] - newm[i]);
                s[i][j] = p;
                ps += p;
            }
            psum[i] = ps;
        }
#pragma unroll
        for (int i = 0; i < 4; i++)
#pragma unroll
            for (int j = 0; j < 4; j++)
                KP[(ty * 4 + i) * QS_STRIDE + tx * 4 + j] = s[i][j];
#pragma unroll
        for (int i = 0; i < 4; i++)
#pragma unroll
            for (int j = 0; j < 4; j++) o[i][j] *= alpha[i];

        __syncthreads();   // (b) red-max reads done, P writes visible
#pragma unroll
        for (int i = 0; i < 4; i++) red[tx * RED_STRIDE + ty * 4 + i] = psum[i];
        __syncthreads();   // (c)

#pragma unroll
        for (int i = 0; i < 4; i++) {
            float tot = 0.f;
#pragma unroll
            for (int t = 0; t < 16; t++) tot += red[t * RED_STRIDE + ty * 4 + i];
            lrow[i] = lrow[i] * alpha[i] + tot;
            mrow[i] = newm[i];
        }

        // O += P @ V
#pragma unroll 8
        for (int c = 0; c < 64; c++) {
            float a[4], v[4];
#pragma unroll
            for (int i = 0; i < 4; i++) a[i] = KP[(ty * 4 + i) * QS_STRIDE + c];
#pragma unroll
            for (int j = 0; j < 4; j++) v[j] = Vs[c * QS_STRIDE + tx * 4 + j];
#pragma unroll
            for (int i = 0; i < 4; i++)
#pragma unroll
                for (int j = 0; j < 4; j++) o[i][j] += a[i] * v[j];
        }
        __syncthreads();   // (d) done with KP/Vs before next tile load
    }

    // Normalize and write out: attn[b, q0+r, h*64 + tx*4 .. +3]
#pragma unroll
    for (int i = 0; i < 4; i++) {
        float inv = 1.f / lrow[i];
        float4 t;
        t.x = o[i][0] * inv; t.y = o[i][1] * inv;
        t.z = o[i][2] * inv; t.w = o[i][3] * inv;
        *(float4*)(attn + (size_t)(b * L_ + q0 + ty * 4 + i) * E_ + basecol + tx * 4) = t;
    }
}

// ---------------------------------------------------------------------------
extern "C" void kernel_launch(void* const* d_in, const int* in_sizes, int n_in,
                              void* d_out, int out_size)
{
    const float* x    = (const float*)d_in[0];
    const float* Wqkv = (const float*)d_in[1];
    const float* bqkv = (const float*)d_in[2];
    const float* Wout = (const float*)d_in[3];
    const float* bout = (const float*)d_in[4];
    float* out = (float*)d_out;

    float* qkv  = nullptr;
    float* attn = nullptr;
    cudaGetSymbolAddress((void**)&qkv,  g_qkv);
    cudaGetSymbolAddress((void**)&attn, g_attn);

    cudaFuncSetAttribute(attention_kernel,
                         cudaFuncAttributeMaxDynamicSharedMemorySize, ATTN_SMEM);

    const int M = B_ * L_;   // 4096

    // 1) qkv = x @ Wqkv^T + bqkv   [4096, 3072]
    gemm_bias<<<dim3((3 * E_) / 128, M / 128), 256>>>(x, Wqkv, bqkv, qkv, M, 3 * E_, E_);

    // 2) attention -> attn [B, L, E]
    attention_kernel<<<dim3(L_ / 64, H_, B_), 256, ATTN_SMEM>>>(qkv, attn);

    // 3) out = attn @ Wout^T + bout  [4096, 1024]
    gemm_bias<<<dim3(E_ / 128, M / 128), 256>>>(attn, Wout, bout, out, M, E_, E_);
}

// round 3
// speedup vs baseline: 1.3989x; 1.3989x over previous
#include <cuda_runtime.h>
#include <cuda_bf16.h>
#include <math.h>
#include <stdint.h>

#define B_  2
#define L_  2048
#define E_  1024
#define H_  16
#define HD_ 64

// Scratch: qkv [B,L,3E], attn [B,L,E]
__device__ float g_qkv[B_ * L_ * 3 * E_];
__device__ float g_attn[B_ * L_ * E_];

// ===========================================================================
// helpers
// ===========================================================================
__device__ __forceinline__ uint32_t smem_to_u32(const void* smem_ptr) {
    uint32_t addr;
    asm("{ .reg .u64 tmp; cvta.to.shared.u64 tmp, %1; cvt.u32.u64 %0, tmp; }"
        : "=r"(addr) : "l"(smem_ptr));
    return addr;
}

__device__ __forceinline__ void ldmatrix_x4(
    uint32_t& r0, uint32_t& r1, uint32_t& r2, uint32_t& r3, uint32_t addr)
{
    asm volatile("ldmatrix.sync.aligned.m8n8.x4.shared.b16 {%0,%1,%2,%3}, [%4];"
        : "=r"(r0), "=r"(r1), "=r"(r2), "=r"(r3) : "r"(addr));
}

__device__ __forceinline__ void mma_bf16(
    float& c0, float& c1, float& c2, float& c3,
    uint32_t a0, uint32_t a1, uint32_t a2, uint32_t a3,
    uint32_t b0, uint32_t b1)
{
    asm volatile(
        "mma.sync.aligned.m16n8k16.row.col.f32.bf16.bf16.f32 "
        "{%0,%1,%2,%3}, {%4,%5,%6,%7}, {%8,%9}, {%0,%1,%2,%3};"
        : "+f"(c0), "+f"(c1), "+f"(c2), "+f"(c3)
        : "r"(a0), "r"(a1), "r"(a2), "r"(a3), "r"(b0), "r"(b1));
}

// ===========================================================================
// Tensor-core GEMM: C[m,n] = sum_k A[m,k]*W[n,k] + bias[n]
// BM=128, BN=128, BK=32. 256 threads / 8 warps; warp tile 64x32.
// bf16x3 split: hi*hi + hi*lo + lo*hi. Double-buffered smem, stride-40 pad.
// ===========================================================================
#define ASTRIDE 40                       // halves per row (conflict-free ldmatrix)
#define TILE_BYTES (128 * ASTRIDE * 2)   // 10240
#define STAGE_BYTES (4 * TILE_BYTES)     // Ahi, Alo, Bhi, Blo
#define GEMM_SMEM (2 * STAGE_BYTES)      // 81920

__global__ __launch_bounds__(256) void gemm_tc(
    const float* __restrict__ A, const float* __restrict__ W,
    const float* __restrict__ bias, float* __restrict__ C,
    int M, int N, int K)
{
    extern __shared__ char sm[];
    const uint32_t sbase = smem_to_u32(sm);

    const int bm   = blockIdx.y * 128;
    const int bn   = blockIdx.x * 128;
    const int tid  = threadIdx.x;
    const int wid  = tid >> 5;
    const int lane = tid & 31;
    const int wm   = wid >> 2;            // 0..1 -> 64-row slab
    const int wn   = wid & 3;             // 0..3 -> 32-col slab

    float c[4][4][4];
#pragma unroll
    for (int i = 0; i < 4; i++)
#pragma unroll
        for (int j = 0; j < 4; j++)
#pragma unroll
            for (int r = 0; r < 4; r++) c[i][j][r] = 0.f;

    const int row_g = tid >> 3;            // 0..31? no: tid>>3 in 0..31, plus i*32
    const int c4    = (tid & 7) * 4;       // fp32 col within 32

    float4 aR[4], bR[4];

    // ---- load tile 0 into regs ----
#pragma unroll
    for (int i = 0; i < 4; i++) {
        int row = row_g + 32 * i;
        aR[i] = *(const float4*)(A + (size_t)(bm + row) * K + c4);
        bR[i] = *(const float4*)(W + (size_t)(bn + row) * K + c4);
    }

    // ---- convert/split + store into stage buffer s ----
    auto store_stage = [&](int s) {
        char* base = sm + s * STAGE_BYTES;
#pragma unroll
        for (int i = 0; i < 4; i++) {
            int row = row_g + 32 * i;
            uint32_t off = (uint32_t)(row * ASTRIDE + c4) * 2;
            {
                float4 t = aR[i];
                __nv_bfloat16 h0 = __float2bfloat16(t.x);
                __nv_bfloat16 h1 = __float2bfloat16(t.y);
                __nv_bfloat16 h2 = __float2bfloat16(t.z);
                __nv_bfloat16 h3 = __float2bfloat16(t.w);
                __nv_bfloat16 l0 = __float2bfloat16(t.x - __bfloat162float(h0));
                __nv_bfloat16 l1 = __float2bfloat16(t.y - __bfloat162float(h1));
                __nv_bfloat16 l2 = __float2bfloat16(t.z - __bfloat162float(h2));
                __nv_bfloat16 l3 = __float2bfloat16(t.w - __bfloat162float(h3));
                *(__nv_bfloat162*)(base + off)                    = __nv_bfloat162(h0, h1);
                *(__nv_bfloat162*)(base + off + 4)                = __nv_bfloat162(h2, h3);
                *(__nv_bfloat162*)(base + TILE_BYTES + off)       = __nv_bfloat162(l0, l1);
                *(__nv_bfloat162*)(base + TILE_BYTES + off + 4)   = __nv_bfloat162(l2, l3);
            }
            {
                float4 t = bR[i];
                __nv_bfloat16 h0 = __float2bfloat16(t.x);
                __nv_bfloat16 h1 = __float2bfloat16(t.y);
                __nv_bfloat16 h2 = __float2bfloat16(t.z);
                __nv_bfloat16 h3 = __float2bfloat16(t.w);
                __nv_bfloat16 l0 = __float2bfloat16(t.x - __bfloat162float(h0));
                __nv_bfloat16 l1 = __float2bfloat16(t.y - __bfloat162float(h1));
                __nv_bfloat16 l2 = __float2bfloat16(t.z - __bfloat162float(h2));
                __nv_bfloat16 l3 = __float2bfloat16(t.w - __bfloat162float(h3));
                *(__nv_bfloat162*)(base + 2*TILE_BYTES + off)     = __nv_bfloat162(h0, h1);
                *(__nv_bfloat162*)(base + 2*TILE_BYTES + off + 4) = __nv_bfloat162(h2, h3);
                *(__nv_bfloat162*)(base + 3*TILE_BYTES + off)     = __nv_bfloat162(l0, l1);
                *(__nv_bfloat162*)(base + 3*TILE_BYTES + off + 4) = __nv_bfloat162(l2, l3);
            }
        }
    };

    store_stage(0);
    __syncthreads();

    const int niter = K / 32;
    for (int iter = 0; iter < niter; iter++) {
        const int cur = iter & 1;
        const uint32_t stage = sbase + cur * STAGE_BYTES;

        // prefetch next tile to registers (overlaps with mma below)
        if (iter + 1 < niter) {
            int k0 = (iter + 1) * 32;
#pragma unroll
            for (int i = 0; i < 4; i++) {
                int row = row_g + 32 * i;
                aR[i] = *(const float4*)(A + (size_t)(bm + row) * K + k0 + c4);
                bR[i] = *(const float4*)(W + (size_t)(bn + row) * K + k0 + c4);
            }
        }

        // ---- MMA over current stage: 2 k-steps of 16 ----
#pragma unroll
        for (int ks = 0; ks < 2; ks++) {
            const int kof = ks * 16;
            uint32_t ahi[4][4], alo[4][4], bhi[4][2], blo[4][2];

            // A fragments: 4 m-atoms, ldmatrix.x4 each (hi and lo)
#pragma unroll
            for (int i = 0; i < 4; i++) {
                int m0 = wm * 64 + i * 16;
                uint32_t ad = stage +
                    (uint32_t)((m0 + (lane & 15)) * ASTRIDE + kof + (lane >> 4) * 8) * 2;
                ldmatrix_x4(ahi[i][0], ahi[i][1], ahi[i][2], ahi[i][3], ad);
                ldmatrix_x4(alo[i][0], alo[i][1], alo[i][2], alo[i][3], ad + TILE_BYTES);
            }
            // B fragments: 4 n-atoms, pairs via ldmatrix.x4 (hi and lo)
#pragma unroll
            for (int jp = 0; jp < 2; jp++) {
                int n0 = wn * 32 + jp * 16;
                int nrow = n0 + ((lane >> 4) << 3) + (lane & 7);
                int bk   = kof + (((lane >> 3) & 1) << 3);
                uint32_t bd = stage + 2 * TILE_BYTES +
                    (uint32_t)(nrow * ASTRIDE + bk) * 2;
                ldmatrix_x4(bhi[jp*2][0], bhi[jp*2][1], bhi[jp*2+1][0], bhi[jp*2+1][1], bd);
                ldmatrix_x4(blo[jp*2][0], blo[jp*2][1], blo[jp*2+1][0], blo[jp*2+1][1],
                            bd + TILE_BYTES);
            }

#pragma unroll
            for (int i = 0; i < 4; i++)
#pragma unroll
                for (int j = 0; j < 4; j++) {
                    mma_bf16(c[i][j][0], c[i][j][1], c[i][j][2], c[i][j][3],
                             ahi[i][0], ahi[i][1], ahi[i][2], ahi[i][3],
                             bhi[j][0], bhi[j][1]);
                    mma_bf16(c[i][j][0], c[i][j][1], c[i][j][2], c[i][j][3],
                             ahi[i][0], ahi[i][1], ahi[i][2], ahi[i][3],
                             blo[j][0], blo[j][1]);
                    mma_bf16(c[i][j][0], c[i][j][1], c[i][j][2], c[i][j][3],
                             alo[i][0], alo[i][1], alo[i][2], alo[i][3],
                             bhi[j][0], bhi[j][1]);
                }
        }

        if (iter + 1 < niter) store_stage(cur ^ 1);
        __syncthreads();
    }

    // ---- epilogue: c[i][j] regs -> global with bias ----
    const int g4 = lane >> 2;       // 0..7
    const int t4 = lane & 3;        // 0..3
#pragma unroll
    for (int i = 0; i < 4; i++) {
        int row0 = bm + wm * 64 + i * 16 + g4;
#pragma unroll
        for (int j = 0; j < 4; j++) {
            int col = bn + wn * 32 + j * 8 + t4 * 2;
            float bx = bias[col], by = bias[col + 1];
            float2 v0 = make_float2(c[i][j][0] + bx, c[i][j][1] + by);
            float2 v1 = make_float2(c[i][j][2] + bx, c[i][j][3] + by);
            *(float2*)(C + (size_t)row0 * N + col)       = v0;
            *(float2*)(C + (size_t)(row0 + 8) * N + col) = v1;
        }
    }
}

// ===========================================================================
// Flash attention (fp32) — unchanged from round 1 (passing version)
// ===========================================================================
#define QS_STRIDE 65
#define RED_STRIDE 68
#define ATTN_SMEM ((3 * 64 * QS_STRIDE + 16 * RED_STRIDE) * 4)

__global__ __launch_bounds__(256) void attention_kernel(
    const float* __restrict__ qkv, float* __restrict__ attn)
{
    extern __shared__ float smf[];
    float* Qs  = smf;
    float* KP  = Qs + 64 * QS_STRIDE;
    float* Vs  = KP + 64 * QS_STRIDE;
    float* red = Vs + 64 * QS_STRIDE;

    const int q0  = blockIdx.x * 64;
    const int h   = blockIdx.y;
    const int b   = blockIdx.z;
    const int tid = threadIdx.x;
    const int ty  = tid >> 4;
    const int tx  = tid & 15;
    const int basecol = h * HD_;

#pragma unroll
    for (int i = 0; i < 4; i++) {
        int v   = tid + 256 * i;
        int row = v >> 4;
        int c   = (v & 15) * 4;
        const float4 t = *(const float4*)(qkv + (size_t)(b * L_ + q0 + row) * (3 * E_) + basecol + c);
        float* dst = &Qs[row * QS_STRIDE + c];
        dst[0] = t.x; dst[1] = t.y; dst[2] = t.z; dst[3] = t.w;
    }

    float o[4][4];
    float mrow[4], lrow[4];
#pragma unroll
    for (int i = 0; i < 4; i++) {
        mrow[i] = -1e30f; lrow[i] = 0.f;
#pragma unroll
        for (int j = 0; j < 4; j++) o[i][j] = 0.f;
    }

    for (int kt = 0; kt < L_; kt += 64) {
#pragma unroll
        for (int i = 0; i < 4; i++) {
            int v   = tid + 256 * i;
            int row = v >> 4;
            int c   = (v & 15) * 4;
            size_t g = (size_t)(b * L_ + kt + row) * (3 * E_) + basecol + c;
            const float4 tk = *(const float4*)(qkv + g + E_);
            const float4 tv = *(const float4*)(qkv + g + 2 * E_);
            float* dk = &KP[row * QS_STRIDE + c];
            dk[0] = tk.x; dk[1] = tk.y; dk[2] = tk.z; dk[3] = tk.w;
            float* dv = &Vs[row * QS_STRIDE + c];
            dv[0] = tv.x; dv[1] = tv.y; dv[2] = tv.z; dv[3] = tv.w;
        }
        __syncthreads();

        float s[4][4];
#pragma unroll
        for (int i = 0; i < 4; i++)
#pragma unroll
            for (int j = 0; j < 4; j++) s[i][j] = 0.f;

#pragma unroll 8
        for (int d = 0; d < 64; d++) {
            float a[4], bb[4];
#pragma unroll
            for (int i = 0; i < 4; i++) a[i]  = Qs[(ty * 4 + i) * QS_STRIDE + d];
#pragma unroll
            for (int j = 0; j < 4; j++) bb[j] = KP[(tx * 4 + j) * QS_STRIDE + d];
#pragma unroll
            for (int i = 0; i < 4; i++)
#pragma unroll
                for (int j = 0; j < 4; j++) s[i][j] += a[i] * bb[j];
        }
#pragma unroll
        for (int i = 0; i < 4; i++)
#pragma unroll
            for (int j = 0; j < 4; j++) s[i][j] *= 0.125f;

#pragma unroll
        for (int i = 0; i < 4; i++) {
            float pm = s[i][0];
#pragma unroll
            for (int j = 1; j < 4; j++) pm = fmaxf(pm, s[i][j]);
            red[tx * RED_STRIDE + ty * 4 + i] = pm;
        }
        __syncthreads();

        float newm[4], alpha[4], psum[4];
#pragma unroll
        for (int i = 0; i < 4; i++) {
            float mm = mrow[i];
#pragma unroll
            for (int t = 0; t < 16; t++) mm = fmaxf(mm, red[t * RED_STRIDE + ty * 4 + i]);
            newm[i]  = mm;
            alpha[i] = __expf(mrow[i] - mm);
        }
#pragma unroll
        for (int i = 0; i < 4; i++) {
            float ps = 0.f;
#pragma unroll
            for (int j = 0; j < 4; j++) {
                float p = __expf(s[i][j] - newm[i]);
                s[i][j] = p;
                ps += p;
            }
            psum[i] = ps;
        }
#pragma unroll
        for (int i = 0; i < 4; i++)
#pragma unroll
            for (int j = 0; j < 4; j++)
                KP[(ty * 4 + i) * QS_STRIDE + tx * 4 + j] = s[i][j];
#pragma unroll
        for (int i = 0; i < 4; i++)
#pragma unroll
            for (int j = 0; j < 4; j++) o[i][j] *= alpha[i];

        __syncthreads();
#pragma unroll
        for (int i = 0; i < 4; i++) red[tx * RED_STRIDE + ty * 4 + i] = psum[i];
        __syncthreads();

#pragma unroll
        for (int i = 0; i < 4; i++) {
            float tot = 0.f;
#pragma unroll
            for (int t = 0; t < 16; t++) tot += red[t * RED_STRIDE + ty * 4 + i];
            lrow[i] = lrow[i] * alpha[i] + tot;
            mrow[i] = newm[i];
        }

#pragma unroll 8
        for (int c2 = 0; c2 < 64; c2++) {
            float a[4], v[4];
#pragma unroll
            for (int i = 0; i < 4; i++) a[i] = KP[(ty * 4 + i) * QS_STRIDE + c2];
#pragma unroll
            for (int j = 0; j < 4; j++) v[j] = Vs[c2 * QS_STRIDE + tx * 4 + j];
#pragma unroll
            for (int i = 0; i < 4; i++)
#pragma unroll
                for (int j = 0; j < 4; j++) o[i][j] += a[i] * v[j];
        }
        __syncthreads();
    }

#pragma unroll
    for (int i = 0; i < 4; i++) {
        float inv = 1.f / lrow[i];
        float4 t;
        t.x = o[i][0] * inv; t.y = o[i][1] * inv;
        t.z = o[i][2] * inv; t.w = o[i][3] * inv;
        *(float4*)(attn + (size_t)(b * L_ + q0 + ty * 4 + i) * E_ + basecol + tx * 4) = t;
    }
}

// ===========================================================================
extern "C" void kernel_launch(void* const* d_in, const int* in_sizes, int n_in,
                              void* d_out, int out_size)
{
    const float* x    = (const float*)d_in[0];
    const float* Wqkv = (const float*)d_in[1];
    const float* bqkv = (const float*)d_in[2];
    const float* Wout = (const float*)d_in[3];
    const float* bout = (const float*)d_in[4];
    float* out = (float*)d_out;

    float* qkv  = nullptr;
    float* attn = nullptr;
    cudaGetSymbolAddress((void**)&qkv,  g_qkv);
    cudaGetSymbolAddress((void**)&attn, g_attn);

    static int attr_done = 0;
    if (!attr_done) {
        cudaFuncSetAttribute(gemm_tc,
                             cudaFuncAttributeMaxDynamicSharedMemorySize, GEMM_SMEM);
        cudaFuncSetAttribute(attention_kernel,
                             cudaFuncAttributeMaxDynamicSharedMemorySize, ATTN_SMEM);
        attr_done = 1;
    }

    const int M = B_ * L_;   // 4096

    // 1) qkv = x @ Wqkv^T + bqkv   [4096, 3072]
    gemm_tc<<<dim3((3 * E_) / 128, M / 128), 256, GEMM_SMEM>>>(x, Wqkv, bqkv, qkv, M, 3 * E_, E_);

    // 2) attention -> attn [B, L, E]
    attention_kernel<<<dim3(L_ / 64, H_, B_), 256, ATTN_SMEM>>>(qkv, attn);

    // 3) out = attn @ Wout^T + bout  [4096, 1024]
    gemm_tc<<<dim3(E_ / 128, M / 128), 256, GEMM_SMEM>>>(attn, Wout, bout, out, M, E_, E_);
}

// round 5
// speedup vs baseline: 2.9954x; 2.1413x over previous
#include <cuda_runtime.h>
#include <cuda_bf16.h>
#include <cuda_fp16.h>
#include <math.h>
#include <stdint.h>

#define B_  2
#define L_  2048
#define E_  1024
#define H_  16
#define HD_ 64

// Scratch: qkv [B,L,3E], attn [B,L,E]
__device__ float g_qkv[B_ * L_ * 3 * E_];
__device__ float g_attn[B_ * L_ * E_];

// ===========================================================================
// helpers
// ===========================================================================
__device__ __forceinline__ uint32_t smem_to_u32(const void* smem_ptr) {
    uint32_t addr;
    asm("{ .reg .u64 tmp; cvta.to.shared.u64 tmp, %1; cvt.u32.u64 %0, tmp; }"
        : "=r"(addr) : "l"(smem_ptr));
    return addr;
}

__device__ __forceinline__ void ldmatrix_x4(
    uint32_t& r0, uint32_t& r1, uint32_t& r2, uint32_t& r3, uint32_t addr)
{
    asm volatile("ldmatrix.sync.aligned.m8n8.x4.shared.b16 {%0,%1,%2,%3}, [%4];"
        : "=r"(r0), "=r"(r1), "=r"(r2), "=r"(r3) : "r"(addr));
}

__device__ __forceinline__ void ldmatrix_x4_trans(
    uint32_t& r0, uint32_t& r1, uint32_t& r2, uint32_t& r3, uint32_t addr)
{
    asm volatile("ldmatrix.sync.aligned.m8n8.x4.trans.shared.b16 {%0,%1,%2,%3}, [%4];"
        : "=r"(r0), "=r"(r1), "=r"(r2), "=r"(r3) : "r"(addr));
}

__device__ __forceinline__ void mma_bf16(
    float& c0, float& c1, float& c2, float& c3,
    uint32_t a0, uint32_t a1, uint32_t a2, uint32_t a3,
    uint32_t b0, uint32_t b1)
{
    asm volatile(
        "mma.sync.aligned.m16n8k16.row.col.f32.bf16.bf16.f32 "
        "{%0,%1,%2,%3}, {%4,%5,%6,%7}, {%8,%9}, {%0,%1,%2,%3};"
        : "+f"(c0), "+f"(c1), "+f"(c2), "+f"(c3)
        : "r"(a0), "r"(a1), "r"(a2), "r"(a3), "r"(b0), "r"(b1));
}

__device__ __forceinline__ void mma_f16(
    float& c0, float& c1, float& c2, float& c3,
    uint32_t a0, uint32_t a1, uint32_t a2, uint32_t a3,
    uint32_t b0, uint32_t b1)
{
    asm volatile(
        "mma.sync.aligned.m16n8k16.row.col.f32.f16.f16.f32 "
        "{%0,%1,%2,%3}, {%4,%5,%6,%7}, {%8,%9}, {%0,%1,%2,%3};"
        : "+f"(c0), "+f"(c1), "+f"(c2), "+f"(c3)
        : "r"(a0), "r"(a1), "r"(a2), "r"(a3), "r"(b0), "r"(b1));
}

__device__ __forceinline__ uint32_t pack_h2(float a, float b) {
    __half2 p = __floats2half2_rn(a, b);
    return *(uint32_t*)&p;
}
__device__ __forceinline__ uint32_t pack_h2_res(float a, float b, uint32_t hi) {
    __half2 h = *(__half2*)&hi;
    float2 f = __half22float2(h);
    return pack_h2(a - f.x, b - f.y);
}

// ===========================================================================
// Tensor-core GEMM (unchanged — passing, rel_err 1.6e-5)
// ===========================================================================
#define ASTRIDE 40
#define TILE_BYTES (128 * ASTRIDE * 2)
#define STAGE_BYTES (4 * TILE_BYTES)
#define GEMM_SMEM (2 * STAGE_BYTES)

__global__ __launch_bounds__(256) void gemm_tc(
    const float* __restrict__ A, const float* __restrict__ W,
    const float* __restrict__ bias, float* __restrict__ C,
    int M, int N, int K)
{
    extern __shared__ char sm[];
    const uint32_t sbase = smem_to_u32(sm);

    const int bm   = blockIdx.y * 128;
    const int bn   = blockIdx.x * 128;
    const int tid  = threadIdx.x;
    const int wid  = tid >> 5;
    const int lane = tid & 31;
    const int wm   = wid >> 2;
    const int wn   = wid & 3;

    float c[4][4][4];
#pragma unroll
    for (int i = 0; i < 4; i++)
#pragma unroll
        for (int j = 0; j < 4; j++)
#pragma unroll
            for (int r = 0; r < 4; r++) c[i][j][r] = 0.f;

    const int row_g = tid >> 3;
    const int c4    = (tid & 7) * 4;

    float4 aR[4], bR[4];

#pragma unroll
    for (int i = 0; i < 4; i++) {
        int row = row_g + 32 * i;
        aR[i] = *(const float4*)(A + (size_t)(bm + row) * K + c4);
        bR[i] = *(const float4*)(W + (size_t)(bn + row) * K + c4);
    }

    auto store_stage = [&](int s) {
        char* base = sm + s * STAGE_BYTES;
#pragma unroll
        for (int i = 0; i < 4; i++) {
            int row = row_g + 32 * i;
            uint32_t off = (uint32_t)(row * ASTRIDE + c4) * 2;
            {
                float4 t = aR[i];
                __nv_bfloat16 h0 = __float2bfloat16(t.x);
                __nv_bfloat16 h1 = __float2bfloat16(t.y);
                __nv_bfloat16 h2 = __float2bfloat16(t.z);
                __nv_bfloat16 h3 = __float2bfloat16(t.w);
                __nv_bfloat16 l0 = __float2bfloat16(t.x - __bfloat162float(h0));
                __nv_bfloat16 l1 = __float2bfloat16(t.y - __bfloat162float(h1));
                __nv_bfloat16 l2 = __float2bfloat16(t.z - __bfloat162float(h2));
                __nv_bfloat16 l3 = __float2bfloat16(t.w - __bfloat162float(h3));
                *(__nv_bfloat162*)(base + off)                    = __nv_bfloat162(h0, h1);
                *(__nv_bfloat162*)(base + off + 4)                = __nv_bfloat162(h2, h3);
                *(__nv_bfloat162*)(base + TILE_BYTES + off)       = __nv_bfloat162(l0, l1);
                *(__nv_bfloat162*)(base + TILE_BYTES + off + 4)   = __nv_bfloat162(l2, l3);
            }
            {
                float4 t = bR[i];
                __nv_bfloat16 h0 = __float2bfloat16(t.x);
                __nv_bfloat16 h1 = __float2bfloat16(t.y);
                __nv_bfloat16 h2 = __float2bfloat16(t.z);
                __nv_bfloat16 h3 = __float2bfloat16(t.w);
                __nv_bfloat16 l0 = __float2bfloat16(t.x - __bfloat162float(h0));
                __nv_bfloat16 l1 = __float2bfloat16(t.y - __bfloat162float(h1));
                __nv_bfloat16 l2 = __float2bfloat16(t.z - __bfloat162float(h2));
                __nv_bfloat16 l3 = __float2bfloat16(t.w - __bfloat162float(h3));
                *(__nv_bfloat162*)(base + 2*TILE_BYTES + off)     = __nv_bfloat162(h0, h1);
                *(__nv_bfloat162*)(base + 2*TILE_BYTES + off + 4) = __nv_bfloat162(h2, h3);
                *(__nv_bfloat162*)(base + 3*TILE_BYTES + off)     = __nv_bfloat162(l0, l1);
                *(__nv_bfloat162*)(base + 3*TILE_BYTES + off + 4) = __nv_bfloat162(l2, l3);
            }
        }
    };

    store_stage(0);
    __syncthreads();

    const int niter = K / 32;
    for (int iter = 0; iter < niter; iter++) {
        const int cur = iter & 1;
        const uint32_t stage = sbase + cur * STAGE_BYTES;

        if (iter + 1 < niter) {
            int k0 = (iter + 1) * 32;
#pragma unroll
            for (int i = 0; i < 4; i++) {
                int row = row_g + 32 * i;
                aR[i] = *(const float4*)(A + (size_t)(bm + row) * K + k0 + c4);
                bR[i] = *(const float4*)(W + (size_t)(bn + row) * K + k0 + c4);
            }
        }

#pragma unroll
        for (int ks = 0; ks < 2; ks++) {
            const int kof = ks * 16;
            uint32_t ahi[4][4], alo[4][4], bhi[4][2], blo[4][2];

#pragma unroll
            for (int i = 0; i < 4; i++) {
                int m0 = wm * 64 + i * 16;
                uint32_t ad = stage +
                    (uint32_t)((m0 + (lane & 15)) * ASTRIDE + kof + (lane >> 4) * 8) * 2;
                ldmatrix_x4(ahi[i][0], ahi[i][1], ahi[i][2], ahi[i][3], ad);
                ldmatrix_x4(alo[i][0], alo[i][1], alo[i][2], alo[i][3], ad + TILE_BYTES);
            }
#pragma unroll
            for (int jp = 0; jp < 2; jp++) {
                int n0 = wn * 32 + jp * 16;
                int nrow = n0 + ((lane >> 4) << 3) + (lane & 7);
                int bk   = kof + (((lane >> 3) & 1) << 3);
                uint32_t bd = stage + 2 * TILE_BYTES +
                    (uint32_t)(nrow * ASTRIDE + bk) * 2;
                ldmatrix_x4(bhi[jp*2][0], bhi[jp*2][1], bhi[jp*2+1][0], bhi[jp*2+1][1], bd);
                ldmatrix_x4(blo[jp*2][0], blo[jp*2][1], blo[jp*2+1][0], blo[jp*2+1][1],
                            bd + TILE_BYTES);
            }

#pragma unroll
            for (int i = 0; i < 4; i++)
#pragma unroll
                for (int j = 0; j < 4; j++) {
                    mma_bf16(c[i][j][0], c[i][j][1], c[i][j][2], c[i][j][3],
                             ahi[i][0], ahi[i][1], ahi[i][2], ahi[i][3],
                             bhi[j][0], bhi[j][1]);
                    mma_bf16(c[i][j][0], c[i][j][1], c[i][j][2], c[i][j][3],
                             ahi[i][0], ahi[i][1], ahi[i][2], ahi[i][3],
                             blo[j][0], blo[j][1]);
                    mma_bf16(c[i][j][0], c[i][j][1], c[i][j][2], c[i][j][3],
                             alo[i][0], alo[i][1], alo[i][2], alo[i][3],
                             bhi[j][0], bhi[j][1]);
                }
        }

        if (iter + 1 < niter) store_stage(cur ^ 1);
        __syncthreads();
    }

    const int g4 = lane >> 2;
    const int t4 = lane & 3;
#pragma unroll
    for (int i = 0; i < 4; i++) {
        int row0 = bm + wm * 64 + i * 16 + g4;
#pragma unroll
        for (int j = 0; j < 4; j++) {
            int col = bn + wn * 32 + j * 8 + t4 * 2;
            float bx = bias[col], by = bias[col + 1];
            float2 v0 = make_float2(c[i][j][0] + bx, c[i][j][1] + by);
            float2 v1 = make_float2(c[i][j][2] + bx, c[i][j][3] + by);
            *(float2*)(C + (size_t)row0 * N + col)       = v0;
            *(float2*)(C + (size_t)(row0 + 8) * N + col) = v1;
        }
    }
}

// ===========================================================================
// Tensor-core flash attention.
// Block: (b, h, 128 q-rows). 8 warps x 16 rows. K-tiles of 64.
// S = Q*K^T via bf16x3 (Q pre-scaled by 1/8).
// P*V via fp16: P split hi+lo (2 mmas), V single fp16.
// smem (halves, stride 72): Qhi[128], Qlo[128], Khi[64], Klo[64], Vh[64]
// ===========================================================================
#define AT_STRIDE 72
#define AQ_HI 0
#define AQ_LO (AQ_HI + 128 * AT_STRIDE * 2)
#define AK_HI (AQ_LO + 128 * AT_STRIDE * 2)
#define AK_LO (AK_HI + 64 * AT_STRIDE * 2)
#define AV_H  (AK_LO + 64 * AT_STRIDE * 2)
#define ATTN_SMEM (AV_H + 64 * AT_STRIDE * 2)

__global__ __launch_bounds__(256) void attention_tc(
    const float* __restrict__ qkv, float* __restrict__ attn)
{
    extern __shared__ char sm[];
    const uint32_t sbase = smem_to_u32(sm);

    const int q0   = blockIdx.x * 128;
    const int h    = blockIdx.y;
    const int b    = blockIdx.z;
    const int tid  = threadIdx.x;
    const int wid  = tid >> 5;
    const int lane = tid & 31;
    const int basecol = h * HD_;

    // ---- load Q tile (128x64), scale by 1/8, split hi/lo -> smem ----
    {
        const int row_g = tid >> 1;
        const int c8    = (tid & 1) * 32;
#pragma unroll
        for (int cc = 0; cc < 32; cc += 4) {
            float4 t = *(const float4*)(qkv + (size_t)(b * L_ + q0 + row_g) * (3 * E_)
                                        + basecol + c8 + cc);
            t.x *= 0.125f; t.y *= 0.125f; t.z *= 0.125f; t.w *= 0.125f;
            __nv_bfloat16 h0 = __float2bfloat16(t.x);
            __nv_bfloat16 h1 = __float2bfloat16(t.y);
            __nv_bfloat16 h2 = __float2bfloat16(t.z);
            __nv_bfloat16 h3 = __float2bfloat16(t.w);
            __nv_bfloat16 l0 = __float2bfloat16(t.x - __bfloat162float(h0));
            __nv_bfloat16 l1 = __float2bfloat16(t.y - __bfloat162float(h1));
            __nv_bfloat16 l2 = __float2bfloat16(t.z - __bfloat162float(h2));
            __nv_bfloat16 l3 = __float2bfloat16(t.w - __bfloat162float(h3));
            uint32_t off = (uint32_t)(row_g * AT_STRIDE + c8 + cc) * 2;
            *(__nv_bfloat162*)(sm + AQ_HI + off)     = __nv_bfloat162(h0, h1);
            *(__nv_bfloat162*)(sm + AQ_HI + off + 4) = __nv_bfloat162(h2, h3);
            *(__nv_bfloat162*)(sm + AQ_LO + off)     = __nv_bfloat162(l0, l1);
            *(__nv_bfloat162*)(sm + AQ_LO + off + 4) = __nv_bfloat162(l2, l3);
        }
    }
    __syncthreads();

    // ---- Q A-fragments -> registers ----
    uint32_t qhi[4][4], qlo[4][4];
#pragma unroll
    for (int ks = 0; ks < 4; ks++) {
        uint32_t ad = sbase + AQ_HI +
            (uint32_t)((wid * 16 + (lane & 15)) * AT_STRIDE + ks * 16 + (lane >> 4) * 8) * 2;
        ldmatrix_x4(qhi[ks][0], qhi[ks][1], qhi[ks][2], qhi[ks][3], ad);
        ldmatrix_x4(qlo[ks][0], qlo[ks][1], qlo[ks][2], qlo[ks][3], ad + (AQ_LO - AQ_HI));
    }

    // ---- per-thread K/V staging ----
    const int kv_row = tid >> 2;
    const int kv_c   = (tid & 3) * 16;
    float4 kR[4], vR[4];

    {
        size_t g = (size_t)(b * L_ + kv_row) * (3 * E_) + basecol + kv_c;
#pragma unroll
        for (int i = 0; i < 4; i++) {
            kR[i] = *(const float4*)(qkv + g + E_     + i * 4);
            vR[i] = *(const float4*)(qkv + g + 2 * E_ + i * 4);
        }
    }

    // ---- state ----
    float o[8][4];
#pragma unroll
    for (int j = 0; j < 8; j++)
#pragma unroll
        for (int r = 0; r < 4; r++) o[j][r] = 0.f;
    float m0 = -1e30f, m1 = -1e30f, l0 = 0.f, l1 = 0.f;

    const int NTILE = L_ / 64;
    for (int it = 0; it < NTILE; it++) {
        // ---- convert + store staged K (bf16 hi/lo) and V (fp16) ----
#pragma unroll
        for (int i = 0; i < 4; i++) {
            uint32_t off = (uint32_t)(kv_row * AT_STRIDE + kv_c + i * 4) * 2;
            {
                float4 t = kR[i];
                __nv_bfloat16 h0 = __float2bfloat16(t.x);
                __nv_bfloat16 h1 = __float2bfloat16(t.y);
                __nv_bfloat16 h2 = __float2bfloat16(t.z);
                __nv_bfloat16 h3 = __float2bfloat16(t.w);
                __nv_bfloat16 l0r = __float2bfloat16(t.x - __bfloat162float(h0));
                __nv_bfloat16 l1r = __float2bfloat16(t.y - __bfloat162float(h1));
                __nv_bfloat16 l2r = __float2bfloat16(t.z - __bfloat162float(h2));
                __nv_bfloat16 l3r = __float2bfloat16(t.w - __bfloat162float(h3));
                *(__nv_bfloat162*)(sm + AK_HI + off)     = __nv_bfloat162(h0, h1);
                *(__nv_bfloat162*)(sm + AK_HI + off + 4) = __nv_bfloat162(h2, h3);
                *(__nv_bfloat162*)(sm + AK_LO + off)     = __nv_bfloat162(l0r, l1r);
                *(__nv_bfloat162*)(sm + AK_LO + off + 4) = __nv_bfloat162(l2r, l3r);
            }
            {
                float4 t = vR[i];
                *(__half2*)(sm + AV_H + off)     = __floats2half2_rn(t.x, t.y);
                *(__half2*)(sm + AV_H + off + 4) = __floats2half2_rn(t.z, t.w);
            }
        }
        __syncthreads();

        // ---- prefetch next tile ----
        if (it + 1 < NTILE) {
            size_t g = (size_t)(b * L_ + (it + 1) * 64 + kv_row) * (3 * E_) + basecol + kv_c;
#pragma unroll
            for (int i = 0; i < 4; i++) {
                kR[i] = *(const float4*)(qkv + g + E_     + i * 4);
                vR[i] = *(const float4*)(qkv + g + 2 * E_ + i * 4);
            }
        }

        // ---- S = Q * K^T (bf16x3) ----
        float s[8][4];
#pragma unroll
        for (int j = 0; j < 8; j++)
#pragma unroll
            for (int r = 0; r < 4; r++) s[j][r] = 0.f;

#pragma unroll
        for (int ks = 0; ks < 4; ks++) {
            const int kof = ks * 16;
            uint32_t bh[8][2], bl[8][2];
#pragma unroll
            for (int jp = 0; jp < 4; jp++) {
                int nrow = jp * 16 + ((lane >> 4) << 3) + (lane & 7);
                int bk   = kof + (((lane >> 3) & 1) << 3);
                uint32_t bd = sbase + AK_HI + (uint32_t)(nrow * AT_STRIDE + bk) * 2;
                ldmatrix_x4(bh[jp*2][0], bh[jp*2][1], bh[jp*2+1][0], bh[jp*2+1][1], bd);
                ldmatrix_x4(bl[jp*2][0], bl[jp*2][1], bl[jp*2+1][0], bl[jp*2+1][1],
                            bd + (AK_LO - AK_HI));
            }
#pragma unroll
            for (int j = 0; j < 8; j++) {
                mma_bf16(s[j][0], s[j][1], s[j][2], s[j][3],
                         qhi[ks][0], qhi[ks][1], qhi[ks][2], qhi[ks][3],
                         bh[j][0], bh[j][1]);
                mma_bf16(s[j][0], s[j][1], s[j][2], s[j][3],
                         qhi[ks][0], qhi[ks][1], qhi[ks][2], qhi[ks][3],
                         bl[j][0], bl[j][1]);
                mma_bf16(s[j][0], s[j][1], s[j][2], s[j][3],
                         qlo[ks][0], qlo[ks][1], qlo[ks][2], qlo[ks][3],
                         bh[j][0], bh[j][1]);
            }
        }

        // ---- online softmax ----
        float rm0 = -1e30f, rm1 = -1e30f;
#pragma unroll
        for (int j = 0; j < 8; j++) {
            rm0 = fmaxf(rm0, fmaxf(s[j][0], s[j][1]));
            rm1 = fmaxf(rm1, fmaxf(s[j][2], s[j][3]));
        }
        rm0 = fmaxf(rm0, __shfl_xor_sync(0xffffffffu, rm0, 1));
        rm0 = fmaxf(rm0, __shfl_xor_sync(0xffffffffu, rm0, 2));
        rm1 = fmaxf(rm1, __shfl_xor_sync(0xffffffffu, rm1, 1));
        rm1 = fmaxf(rm1, __shfl_xor_sync(0xffffffffu, rm1, 2));

        float nm0 = fmaxf(m0, rm0), nm1 = fmaxf(m1, rm1);
        float a0 = __expf(m0 - nm0), a1 = __expf(m1 - nm1);

        float rs0 = 0.f, rs1 = 0.f;
#pragma unroll
        for (int j = 0; j < 8; j++) {
            s[j][0] = __expf(s[j][0] - nm0);
            s[j][1] = __expf(s[j][1] - nm0);
            s[j][2] = __expf(s[j][2] - nm1);
            s[j][3] = __expf(s[j][3] - nm1);
            rs0 += s[j][0] + s[j][1];
            rs1 += s[j][2] + s[j][3];
        }
        rs0 += __shfl_xor_sync(0xffffffffu, rs0, 1);
        rs0 += __shfl_xor_sync(0xffffffffu, rs0, 2);
        rs1 += __shfl_xor_sync(0xffffffffu, rs1, 1);
        rs1 += __shfl_xor_sync(0xffffffffu, rs1, 2);

        l0 = l0 * a0 + rs0;  m0 = nm0;
        l1 = l1 * a1 + rs1;  m1 = nm1;

#pragma unroll
        for (int j = 0; j < 8; j++) {
            o[j][0] *= a0; o[j][1] *= a0;
            o[j][2] *= a1; o[j][3] *= a1;
        }

        // ---- O += P * V  (fp16: P hi+lo, V single) ----
#pragma unroll
        for (int kk = 0; kk < 4; kk++) {
            uint32_t ph0 = pack_h2(s[2*kk][0],   s[2*kk][1]);
            uint32_t ph1 = pack_h2(s[2*kk][2],   s[2*kk][3]);
            uint32_t ph2 = pack_h2(s[2*kk+1][0], s[2*kk+1][1]);
            uint32_t ph3 = pack_h2(s[2*kk+1][2], s[2*kk+1][3]);
            uint32_t pl0 = pack_h2_res(s[2*kk][0],   s[2*kk][1],   ph0);
            uint32_t pl1 = pack_h2_res(s[2*kk][2],   s[2*kk][3],   ph1);
            uint32_t pl2 = pack_h2_res(s[2*kk+1][0], s[2*kk+1][1], ph2);
            uint32_t pl3 = pack_h2_res(s[2*kk+1][2], s[2*kk+1][3], ph3);
#pragma unroll
            for (int jp = 0; jp < 4; jp++) {
                int vrow = kk * 16 + (((lane >> 3) & 1) << 3) + (lane & 7);
                int vcol = jp * 16 + ((lane >> 4) << 3);
                uint32_t vd = sbase + AV_H + (uint32_t)(vrow * AT_STRIDE + vcol) * 2;
                uint32_t v0, v1, v2, v3;
                ldmatrix_x4_trans(v0, v1, v2, v3, vd);
                mma_f16(o[jp*2][0],   o[jp*2][1],   o[jp*2][2],   o[jp*2][3],
                        ph0, ph1, ph2, ph3, v0, v1);
                mma_f16(o[jp*2][0],   o[jp*2][1],   o[jp*2][2],   o[jp*2][3],
                        pl0, pl1, pl2, pl3, v0, v1);
                mma_f16(o[jp*2+1][0], o[jp*2+1][1], o[jp*2+1][2], o[jp*2+1][3],
                        ph0, ph1, ph2, ph3, v2, v3);
                mma_f16(o[jp*2+1][0], o[jp*2+1][1], o[jp*2+1][2], o[jp*2+1][3],
                        pl0, pl1, pl2, pl3, v2, v3);
            }
        }
        __syncthreads();
    }

    // ---- normalize + write out ----
    float inv0 = 1.f / l0, inv1 = 1.f / l1;
    const int orow = b * L_ + q0 + wid * 16 + (lane >> 2);
#pragma unroll
    for (int j = 0; j < 8; j++) {
        int col = basecol + j * 8 + (lane & 3) * 2;
        *(float2*)(attn + (size_t)orow * E_ + col) =
            make_float2(o[j][0] * inv0, o[j][1] * inv0);
        *(float2*)(attn + (size_t)(orow + 8) * E_ + col) =
            make_float2(o[j][2] * inv1, o[j][3] * inv1);
    }
}

// ===========================================================================
extern "C" void kernel_launch(void* const* d_in, const int* in_sizes, int n_in,
                              void* d_out, int out_size)
{
    const float* x    = (const float*)d_in[0];
    const float* Wqkv = (const float*)d_in[1];
    const float* bqkv = (const float*)d_in[2];
    const float* Wout = (const float*)d_in[3];
    const float* bout = (const float*)d_in[4];
    float* out = (float*)d_out;

    float* qkv  = nullptr;
    float* attn = nullptr;
    cudaGetSymbolAddress((void**)&qkv,  g_qkv);
    cudaGetSymbolAddress((void**)&attn, g_attn);

    static int attr_done = 0;
    if (!attr_done) {
        cudaFuncSetAttribute(gemm_tc,
                             cudaFuncAttributeMaxDynamicSharedMemorySize, GEMM_SMEM);
        cudaFuncSetAttribute(attention_tc,
                             cudaFuncAttributeMaxDynamicSharedMemorySize, ATTN_SMEM);
        attr_done = 1;
    }

    const int M = B_ * L_;   // 4096

    // 1) qkv = x @ Wqkv^T + bqkv   [4096, 3072]
    gemm_tc<<<dim3((3 * E_) / 128, M / 128), 256, GEMM_SMEM>>>(x, Wqkv, bqkv, qkv, M, 3 * E_, E_);

    // 2) attention -> attn [B, L, E]
    attention_tc<<<dim3(L_ / 128, H_, B_), 256, ATTN_SMEM>>>(qkv, attn);

    // 3) out = attn @ Wout^T + bout  [4096, 1024]
    gemm_tc<<<dim3(E_ / 128, M / 128), 256, GEMM_SMEM>>>(attn, Wout, bout, out, M, E_, E_);
}

// round 7
// speedup vs baseline: 3.1084x; 1.0377x over previous
#include <cuda_runtime.h>
#include <cuda_bf16.h>
#include <cuda_fp16.h>
#include <math.h>
#include <stdint.h>

#define B_  2
#define L_  2048
#define E_  1024
#define H_  16
#define HD_ 64
#define M_  (B_ * L_)   // 4096

// ---------------------------------------------------------------------------
// Scratch (bf16 hi/lo split world)
// ---------------------------------------------------------------------------
__device__ __align__(16) __nv_bfloat16 g_xhi[M_ * E_];
__device__ __align__(16) __nv_bfloat16 g_xlo[M_ * E_];
__device__ __align__(16) __nv_bfloat16 g_wqkvhi[3 * E_ * E_];
__device__ __align__(16) __nv_bfloat16 g_wqkvlo[3 * E_ * E_];
__device__ __align__(16) __nv_bfloat16 g_wohi[E_ * E_];
__device__ __align__(16) __nv_bfloat16 g_wolo[E_ * E_];
__device__ __align__(16) __nv_bfloat16 g_qhi[M_ * E_];   // Q * 0.125, split
__device__ __align__(16) __nv_bfloat16 g_qlo[M_ * E_];
__device__ __align__(16) __nv_bfloat16 g_khi[M_ * E_];
__device__ __align__(16) __nv_bfloat16 g_klo[M_ * E_];
__device__ __align__(16) __half        g_v16[M_ * E_];
__device__ __align__(16) __nv_bfloat16 g_ahi[M_ * E_];   // attention out, split
__device__ __align__(16) __nv_bfloat16 g_alo[M_ * E_];

// ---------------------------------------------------------------------------
// helpers
// ---------------------------------------------------------------------------
__device__ __forceinline__ uint32_t smem_to_u32(const void* p) {
    uint32_t a;
    asm("{ .reg .u64 t; cvta.to.shared.u64 t, %1; cvt.u32.u64 %0, t; }" : "=r"(a) : "l"(p));
    return a;
}
__device__ __forceinline__ void cp_async16(uint32_t dst, const void* src) {
    asm volatile("cp.async.cg.shared.global [%0], [%1], 16;" :: "r"(dst), "l"(src));
}
#define CP_COMMIT() asm volatile("cp.async.commit_group;")
#define CP_WAIT1()  asm volatile("cp.async.wait_group 1;")
#define CP_WAIT0()  asm volatile("cp.async.wait_group 0;")

__device__ __forceinline__ void ldmatrix_x4(
    uint32_t& r0, uint32_t& r1, uint32_t& r2, uint32_t& r3, uint32_t addr)
{
    asm volatile("ldmatrix.sync.aligned.m8n8.x4.shared.b16 {%0,%1,%2,%3}, [%4];"
        : "=r"(r0), "=r"(r1), "=r"(r2), "=r"(r3) : "r"(addr));
}
__device__ __forceinline__ void ldmatrix_x4_trans(
    uint32_t& r0, uint32_t& r1, uint32_t& r2, uint32_t& r3, uint32_t addr)
{
    asm volatile("ldmatrix.sync.aligned.m8n8.x4.trans.shared.b16 {%0,%1,%2,%3}, [%4];"
        : "=r"(r0), "=r"(r1), "=r"(r2), "=r"(r3) : "r"(addr));
}
__device__ __forceinline__ void mma_bf16(
    float& c0, float& c1, float& c2, float& c3,
    uint32_t a0, uint32_t a1, uint32_t a2, uint32_t a3, uint32_t b0, uint32_t b1)
{
    asm volatile(
        "mma.sync.aligned.m16n8k16.row.col.f32.bf16.bf16.f32 "
        "{%0,%1,%2,%3}, {%4,%5,%6,%7}, {%8,%9}, {%0,%1,%2,%3};"
        : "+f"(c0), "+f"(c1), "+f"(c2), "+f"(c3)
        : "r"(a0), "r"(a1), "r"(a2), "r"(a3), "r"(b0), "r"(b1));
}
__device__ __forceinline__ void mma_f16(
    float& c0, float& c1, float& c2, float& c3,
    uint32_t a0, uint32_t a1, uint32_t a2, uint32_t a3, uint32_t b0, uint32_t b1)
{
    asm volatile(
        "mma.sync.aligned.m16n8k16.row.col.f32.f16.f16.f32 "
        "{%0,%1,%2,%3}, {%4,%5,%6,%7}, {%8,%9}, {%0,%1,%2,%3};"
        : "+f"(c0), "+f"(c1), "+f"(c2), "+f"(c3)
        : "r"(a0), "r"(a1), "r"(a2), "r"(a3), "r"(b0), "r"(b1));
}
__device__ __forceinline__ uint32_t pack_h2(float a, float b) {
    __half2 p = __floats2half2_rn(a, b);
    return *(uint32_t*)&p;
}
__device__ __forceinline__ uint32_t pack_h2_res(float a, float b, uint32_t hi) {
    __half2 h = *(__half2*)&hi;
    float2 f = __half22float2(h);
    return pack_h2(a - f.x, b - f.y);
}
__device__ __forceinline__ void store_split2(
    __nv_bfloat16* hi, __nv_bfloat16* lo, size_t idx, float a, float b)
{
    __nv_bfloat16 ha = __float2bfloat16(a);
    __nv_bfloat16 hb = __float2bfloat16(b);
    *(__nv_bfloat162*)(hi + idx) = __nv_bfloat162(ha, hb);
    *(__nv_bfloat162*)(lo + idx) = __nv_bfloat162(
        __float2bfloat16(a - __bfloat162float(ha)),
        __float2bfloat16(b - __bfloat162float(hb)));
}

// ---------------------------------------------------------------------------
// Prepass: fp32 -> (hi, lo) bf16
// ---------------------------------------------------------------------------
__global__ void conv_split(const float4* __restrict__ src,
                           __nv_bfloat162* __restrict__ hi,
                           __nv_bfloat162* __restrict__ lo, int n4)
{
    int i = blockIdx.x * blockDim.x + threadIdx.x;
    if (i >= n4) return;
    float4 t = src[i];
    __nv_bfloat16 h0 = __float2bfloat16(t.x);
    __nv_bfloat16 h1 = __float2bfloat16(t.y);
    __nv_bfloat16 h2 = __float2bfloat16(t.z);
    __nv_bfloat16 h3 = __float2bfloat16(t.w);
    hi[2*i]   = __nv_bfloat162(h0, h1);
    hi[2*i+1] = __nv_bfloat162(h2, h3);
    lo[2*i]   = __nv_bfloat162(__float2bfloat16(t.x - __bfloat162float(h0)),
                               __float2bfloat16(t.y - __bfloat162float(h1)));
    lo[2*i+1] = __nv_bfloat162(__float2bfloat16(t.z - __bfloat162float(h2)),
                               __float2bfloat16(t.w - __bfloat162float(h3)));
}

// ---------------------------------------------------------------------------
// GEMM on pre-split bf16: C = A @ W^T (+bias).
// BM=128, BN=128, BK=32; 256 threads, 8 warps (wm 0..1 x wn 0..3), bf16x3.
// cp.async double-buffered. EPI=0: fp32+bias -> Cf. EPI=1: qkv split epilogue.
// ---------------------------------------------------------------------------
#define GT_STRIDE 40
#define GT_TILE   (128 * GT_STRIDE * 2)   // 10240 B
#define GT_STAGE  (4 * GT_TILE)           // 40960 B
#define GEMM_SMEM (2 * GT_STAGE)          // 81920 B

template<int EPI>
__global__ __launch_bounds__(256, 2) void gemm_split(
    const __nv_bfloat16* __restrict__ Ahi, const __nv_bfloat16* __restrict__ Alo,
    const __nv_bfloat16* __restrict__ Bhi, const __nv_bfloat16* __restrict__ Blo,
    const float* __restrict__ bias, float* __restrict__ Cf,
    __nv_bfloat16* __restrict__ qhi, __nv_bfloat16* __restrict__ qlo,
    __nv_bfloat16* __restrict__ khi, __nv_bfloat16* __restrict__ klo,
    __half* __restrict__ v16,
    int M, int N, int K)
{
    extern __shared__ char smg[];
    const uint32_t sbase = smem_to_u32(smg);

    const int bm   = blockIdx.y * 128;
    const int bn   = blockIdx.x * 128;
    const int tid  = threadIdx.x;
    const int wid  = tid >> 5;
    const int lane = tid & 31;
    const int wm   = wid >> 2;
    const int wn   = wid & 3;

    float c[4][4][4];
#pragma unroll
    for (int i = 0; i < 4; i++)
#pragma unroll
        for (int j = 0; j < 4; j++)
#pragma unroll
            for (int r = 0; r < 4; r++) c[i][j][r] = 0.f;

    auto load_stage = [&](int s, int k0) {
        const uint32_t base = sbase + s * GT_STAGE;
        const __nv_bfloat16* srcs[4] = {
            Ahi + (size_t)bm * K + k0, Alo + (size_t)bm * K + k0,
            Bhi + (size_t)bn * K + k0, Blo + (size_t)bn * K + k0 };
#pragma unroll
        for (int t = 0; t < 4; t++) {
#pragma unroll
            for (int i = 0; i < 2; i++) {
                int chunk = tid * 2 + i;        // 0..511
                int row   = chunk >> 2;
                int cc    = chunk & 3;
                cp_async16(base + t * GT_TILE + row * (GT_STRIDE * 2) + cc * 16,
                           srcs[t] + (size_t)row * K + cc * 8);
            }
        }
    };

    load_stage(0, 0);
    CP_COMMIT();

    const int niter = K / 32;
    for (int it = 0; it < niter; it++) {
        if (it + 1 < niter) { load_stage((it + 1) & 1, (it + 1) * 32); CP_COMMIT(); CP_WAIT1(); }
        else                { CP_WAIT0(); }
        __syncthreads();

        const uint32_t stage = sbase + (it & 1) * GT_STAGE;
#pragma unroll
        for (int ks = 0; ks < 2; ks++) {
            const int kof = ks * 16;
            uint32_t ahi[4][4], alo[4][4], bhi[4][2], blo[4][2];
#pragma unroll
            for (int i = 0; i < 4; i++) {
                int m0 = wm * 64 + i * 16;
                uint32_t ad = stage +
                    (uint32_t)((m0 + (lane & 15)) * GT_STRIDE + kof + (lane >> 4) * 8) * 2;
                ldmatrix_x4(ahi[i][0], ahi[i][1], ahi[i][2], ahi[i][3], ad);
                ldmatrix_x4(alo[i][0], alo[i][1], alo[i][2], alo[i][3], ad + GT_TILE);
            }
#pragma unroll
            for (int jp = 0; jp < 2; jp++) {
                int n0 = wn * 32 + jp * 16;
                int nrow = n0 + ((lane >> 4) << 3) + (lane & 7);
                int bk   = kof + (((lane >> 3) & 1) << 3);
                uint32_t bd = stage + 2 * GT_TILE + (uint32_t)(nrow * GT_STRIDE + bk) * 2;
                ldmatrix_x4(bhi[jp*2][0], bhi[jp*2][1], bhi[jp*2+1][0], bhi[jp*2+1][1], bd);
                ldmatrix_x4(blo[jp*2][0], blo[jp*2][1], blo[jp*2+1][0], blo[jp*2+1][1],
                            bd + GT_TILE);
            }
#pragma unroll
            for (int i = 0; i < 4; i++)
#pragma unroll
                for (int j = 0; j < 4; j++) {
                    mma_bf16(c[i][j][0], c[i][j][1], c[i][j][2], c[i][j][3],
                             ahi[i][0], ahi[i][1], ahi[i][2], ahi[i][3],
                             bhi[j][0], bhi[j][1]);
                    mma_bf16(c[i][j][0], c[i][j][1], c[i][j][2], c[i][j][3],
                             ahi[i][0], ahi[i][1], ahi[i][2], ahi[i][3],
                             blo[j][0], blo[j][1]);
                    mma_bf16(c[i][j][0], c[i][j][1], c[i][j][2], c[i][j][3],
                             alo[i][0], alo[i][1], alo[i][2], alo[i][3],
                             bhi[j][0], bhi[j][1]);
                }
        }
        __syncthreads();
    }

    // ---- epilogue ----
    const int g4 = lane >> 2;
    const int t4 = lane & 3;
    if (EPI == 0) {
#pragma unroll
        for (int i = 0; i < 4; i++) {
            int row0 = bm + wm * 64 + i * 16 + g4;
#pragma unroll
            for (int j = 0; j < 4; j++) {
                int col = bn + wn * 32 + j * 8 + t4 * 2;
                float bx = bias[col], by = bias[col + 1];
                *(float2*)(Cf + (size_t)row0 * N + col) =
                    make_float2(c[i][j][0] + bx, c[i][j][1] + by);
                *(float2*)(Cf + (size_t)(row0 + 8) * N + col) =
                    make_float2(c[i][j][2] + bx, c[i][j][3] + by);
            }
        }
    } else {
        const int seg     = bn >> 10;          // 0=Q, 1=K, 2=V
        const int segbase = bn & 1023;
#pragma unroll
        for (int i = 0; i < 4; i++) {
            int row0 = bm + wm * 64 + i * 16 + g4;
#pragma unroll
            for (int j = 0; j < 4; j++) {
                int colg = bn + wn * 32 + j * 8 + t4 * 2;
                int cols = segbase + wn * 32 + j * 8 + t4 * 2;
                float bx = bias[colg], by = bias[colg + 1];
                float v0 = c[i][j][0] + bx, v1 = c[i][j][1] + by;
                float v2 = c[i][j][2] + bx, v3 = c[i][j][3] + by;
                size_t i0 = (size_t)row0 * E_ + cols;
                size_t i1 = (size_t)(row0 + 8) * E_ + cols;
                if (seg == 0) {
                    store_split2(qhi, qlo, i0, v0 * 0.125f, v1 * 0.125f);
                    store_split2(qhi, qlo, i1, v2 * 0.125f, v3 * 0.125f);
                } else if (seg == 1) {
                    store_split2(khi, klo, i0, v0, v1);
                    store_split2(khi, klo, i1, v2, v3);
                } else {
                    *(__half2*)(v16 + i0) = __floats2half2_rn(v0, v1);
                    *(__half2*)(v16 + i1) = __floats2half2_rn(v2, v3);
                }
            }
        }
    }
}

// ---------------------------------------------------------------------------
// Flash attention on pre-converted operands. Block: (b, h, 128 q-rows).
// Q frags direct from global; K/V tiles via cp.async double buffer.
// ---------------------------------------------------------------------------
#define AT_STRIDE 72
#define AT_TILE   (64 * AT_STRIDE * 2)     // 9216
#define AT_STAGE  (3 * AT_TILE)            // 27648
#define ATTN_SMEM (2 * AT_STAGE)           // 55296

__global__ __launch_bounds__(256) void attention_tc(
    const __nv_bfloat16* __restrict__ qh, const __nv_bfloat16* __restrict__ ql,
    const __nv_bfloat16* __restrict__ kh, const __nv_bfloat16* __restrict__ kl,
    const __half* __restrict__ v16,
    __nv_bfloat16* __restrict__ ahi, __nv_bfloat16* __restrict__ alo)
{
    extern __shared__ char sma[];
    const uint32_t sbase = smem_to_u32(sma);

    const int q0   = blockIdx.x * 128;
    const int h    = blockIdx.y;
    const int b    = blockIdx.z;
    const int tid  = threadIdx.x;
    const int wid  = tid >> 5;
    const int lane = tid & 31;
    const int basecol = h * HD_;

    // ---- Q fragments directly from global (mapping == ldmatrix A-frag) ----
    uint32_t qfh[4][4], qfl[4][4];
    {
        const int r0 = b * L_ + q0 + wid * 16 + (lane >> 2);
        const int c0 = basecol + (lane & 3) * 2;
#pragma unroll
        for (int ks = 0; ks < 4; ks++) {
            size_t i00 = (size_t)r0 * E_ + c0 + ks * 16;
            qfh[ks][0] = *(const uint32_t*)(qh + i00);
            qfh[ks][1] = *(const uint32_t*)(qh + i00 + 8 * E_);
            qfh[ks][2] = *(const uint32_t*)(qh + i00 + 8);
            qfh[ks][3] = *(const uint32_t*)(qh + i00 + 8 * E_ + 8);
            qfl[ks][0] = *(const uint32_t*)(ql + i00);
            qfl[ks][1] = *(const uint32_t*)(ql + i00 + 8 * E_);
            qfl[ks][2] = *(const uint32_t*)(ql + i00 + 8);
            qfl[ks][3] = *(const uint32_t*)(ql + i00 + 8 * E_ + 8);
        }
    }

    auto load_kv = [&](int s, int kt) {
        const uint32_t base = sbase + s * AT_STAGE;
        const int rowg = b * L_ + kt;
#pragma unroll
        for (int i = 0; i < 2; i++) {
            int chunk = tid * 2 + i;        // 0..511
            int row   = chunk >> 3;
            int cc    = chunk & 7;
            size_t src = (size_t)(rowg + row) * E_ + basecol + cc * 8;
            uint32_t doff = row * (AT_STRIDE * 2) + cc * 16;
            cp_async16(base + doff,               kh  + src);
            cp_async16(base + AT_TILE + doff,     kl  + src);
            cp_async16(base + 2 * AT_TILE + doff, v16 + src);
        }
    };

    load_kv(0, 0);
    CP_COMMIT();

    float o[8][4];
#pragma unroll
    for (int j = 0; j < 8; j++)
#pragma unroll
        for (int r = 0; r < 4; r++) o[j][r] = 0.f;
    float m0 = -1e30f, m1 = -1e30f, l0 = 0.f, l1 = 0.f;

    const int NTILE = L_ / 64;
    for (int it = 0; it < NTILE; it++) {
        if (it + 1 < NTILE) { load_kv((it + 1) & 1, (it + 1) * 64); CP_COMMIT(); CP_WAIT1(); }
        else                { CP_WAIT0(); }
        __syncthreads();

        const uint32_t stage = sbase + (it & 1) * AT_STAGE;

        // ---- S = Q * K^T (bf16x3) ----
        float s[8][4];
#pragma unroll
        for (int j = 0; j < 8; j++)
#pragma unroll
            for (int r = 0; r < 4; r++) s[j][r] = 0.f;

#pragma unroll
        for (int ks = 0; ks < 4; ks++) {
            const int kof = ks * 16;
            uint32_t bh[8][2], bl[8][2];
#pragma unroll
            for (int jp = 0; jp < 4; jp++) {
                int nrow = jp * 16 + ((lane >> 4) << 3) + (lane & 7);
                int bk   = kof + (((lane >> 3) & 1) << 3);
                uint32_t bd = stage + (uint32_t)(nrow * AT_STRIDE + bk) * 2;
                ldmatrix_x4(bh[jp*2][0], bh[jp*2][1], bh[jp*2+1][0], bh[jp*2+1][1], bd);
                ldmatrix_x4(bl[jp*2][0], bl[jp*2][1], bl[jp*2+1][0], bl[jp*2+1][1],
                            bd + AT_TILE);
            }
#pragma unroll
            for (int j = 0; j < 8; j++) {
                mma_bf16(s[j][0], s[j][1], s[j][2], s[j][3],
                         qfh[ks][0], qfh[ks][1], qfh[ks][2], qfh[ks][3],
                         bh[j][0], bh[j][1]);
                mma_bf16(s[j][0], s[j][1], s[j][2], s[j][3],
                         qfh[ks][0], qfh[ks][1], qfh[ks][2], qfh[ks][3],
                         bl[j][0], bl[j][1]);
                mma_bf16(s[j][0], s[j][1], s[j][2], s[j][3],
                         qfl[ks][0], qfl[ks][1], qfl[ks][2], qfl[ks][3],
                         bh[j][0], bh[j][1]);
            }
        }

        // ---- online softmax ----
        float rm0 = -1e30f, rm1 = -1e30f;
#pragma unroll
        for (int j = 0; j < 8; j++) {
            rm0 = fmaxf(rm0, fmaxf(s[j][0], s[j][1]));
            rm1 = fmaxf(rm1, fmaxf(s[j][2], s[j][3]));
        }
        rm0 = fmaxf(rm0, __shfl_xor_sync(0xffffffffu, rm0, 1));
        rm0 = fmaxf(rm0, __shfl_xor_sync(0xffffffffu, rm0, 2));
        rm1 = fmaxf(rm1, __shfl_xor_sync(0xffffffffu, rm1, 1));
        rm1 = fmaxf(rm1, __shfl_xor_sync(0xffffffffu, rm1, 2));

        float nm0 = fmaxf(m0, rm0), nm1 = fmaxf(m1, rm1);
        float a0 = __expf(m0 - nm0), a1 = __expf(m1 - nm1);

        float rs0 = 0.f, rs1 = 0.f;
#pragma unroll
        for (int j = 0; j < 8; j++) {
            s[j][0] = __expf(s[j][0] - nm0);
            s[j][1] = __expf(s[j][1] - nm0);
            s[j][2] = __expf(s[j][2] - nm1);
            s[j][3] = __expf(s[j][3] - nm1);
            rs0 += s[j][0] + s[j][1];
            rs1 += s[j][2] + s[j][3];
        }
        rs0 += __shfl_xor_sync(0xffffffffu, rs0, 1);
        rs0 += __shfl_xor_sync(0xffffffffu, rs0, 2);
        rs1 += __shfl_xor_sync(0xffffffffu, rs1, 1);
        rs1 += __shfl_xor_sync(0xffffffffu, rs1, 2);

        l0 = l0 * a0 + rs0;  m0 = nm0;
        l1 = l1 * a1 + rs1;  m1 = nm1;

#pragma unroll
        for (int j = 0; j < 8; j++) {
            o[j][0] *= a0; o[j][1] *= a0;
            o[j][2] *= a1; o[j][3] *= a1;
        }

        // ---- O += P * V (fp16: P hi+lo) ----
#pragma unroll
        for (int kk = 0; kk < 4; kk++) {
            uint32_t ph0 = pack_h2(s[2*kk][0],   s[2*kk][1]);
            uint32_t ph1 = pack_h2(s[2*kk][2],   s[2*kk][3]);
            uint32_t ph2 = pack_h2(s[2*kk+1][0], s[2*kk+1][1]);
            uint32_t ph3 = pack_h2(s[2*kk+1][2], s[2*kk+1][3]);
            uint32_t pl0 = pack_h2_res(s[2*kk][0],   s[2*kk][1],   ph0);
            uint32_t pl1 = pack_h2_res(s[2*kk][2],   s[2*kk][3],   ph1);
            uint32_t pl2 = pack_h2_res(s[2*kk+1][0], s[2*kk+1][1], ph2);
            uint32_t pl3 = pack_h2_res(s[2*kk+1][2], s[2*kk+1][3], ph3);
#pragma unroll
            for (int jp = 0; jp < 4; jp++) {
                int vrow = kk * 16 + (((lane >> 3) & 1) << 3) + (lane & 7);
                int vcol = jp * 16 + ((lane >> 4) << 3);
                uint32_t vd = stage + 2 * AT_TILE + (uint32_t)(vrow * AT_STRIDE + vcol) * 2;
                uint32_t v0, v1, v2, v3;
                ldmatrix_x4_trans(v0, v1, v2, v3, vd);
                mma_f16(o[jp*2][0],   o[jp*2][1],   o[jp*2][2],   o[jp*2][3],
                        ph0, ph1, ph2, ph3, v0, v1);
                mma_f16(o[jp*2][0],   o[jp*2][1],   o[jp*2][2],   o[jp*2][3],
                        pl0, pl1, pl2, pl3, v0, v1);
                mma_f16(o[jp*2+1][0], o[jp*2+1][1], o[jp*2+1][2], o[jp*2+1][3],
                        ph0, ph1, ph2, ph3, v2, v3);
                mma_f16(o[jp*2+1][0], o[jp*2+1][1], o[jp*2+1][2], o[jp*2+1][3],
                        pl0, pl1, pl2, pl3, v2, v3);
            }
        }
        __syncthreads();
    }

    // ---- normalize + split-write ----
    float inv0 = 1.f / l0, inv1 = 1.f / l1;
    const int orow = b * L_ + q0 + wid * 16 + (lane >> 2);
#pragma unroll
    for (int j = 0; j < 8; j++) {
        int col = basecol + j * 8 + (lane & 3) * 2;
        store_split2(ahi, alo, (size_t)orow * E_ + col,       o[j][0] * inv0, o[j][1] * inv0);
        store_split2(ahi, alo, (size_t)(orow + 8) * E_ + col, o[j][2] * inv1, o[j][3] * inv1);
    }
}

// ---------------------------------------------------------------------------
extern "C" void kernel_launch(void* const* d_in, const int* in_sizes, int n_in,
                              void* d_out, int out_size)
{
    const float* x    = (const float*)d_in[0];
    const float* Wqkv = (const float*)d_in[1];
    const float* bqkv = (const float*)d_in[2];
    const float* Wout = (const float*)d_in[3];
    const float* bout = (const float*)d_in[4];
    float* out = (float*)d_out;

    __nv_bfloat16 *xhi, *xlo, *wqh, *wql, *woh, *wol;
    __nv_bfloat16 *qhi, *qlo, *khi, *klo, *ahi, *alo;
    __half *v16;
    cudaGetSymbolAddress((void**)&xhi, g_xhi);   cudaGetSymbolAddress((void**)&xlo, g_xlo);
    cudaGetSymbolAddress((void**)&wqh, g_wqkvhi); cudaGetSymbolAddress((void**)&wql, g_wqkvlo);
    cudaGetSymbolAddress((void**)&woh, g_wohi);  cudaGetSymbolAddress((void**)&wol, g_wolo);
    cudaGetSymbolAddress((void**)&qhi, g_qhi);   cudaGetSymbolAddress((void**)&qlo, g_qlo);
    cudaGetSymbolAddress((void**)&khi, g_khi);   cudaGetSymbolAddress((void**)&klo, g_klo);
    cudaGetSymbolAddress((void**)&v16, g_v16);
    cudaGetSymbolAddress((void**)&ahi, g_ahi);   cudaGetSymbolAddress((void**)&alo, g_alo);

    static int attr_done = 0;
    if (!attr_done) {
        cudaFuncSetAttribute(gemm_split<0>,
                             cudaFuncAttributeMaxDynamicSharedMemorySize, GEMM_SMEM);
        cudaFuncSetAttribute(gemm_split<1>,
                             cudaFuncAttributeMaxDynamicSharedMemorySize, GEMM_SMEM);
        cudaFuncSetAttribute(attention_tc,
                             cudaFuncAttributeMaxDynamicSharedMemorySize, ATTN_SMEM);
        attr_done = 1;
    }

    // 0) prepass splits
    conv_split<<<(M_ * E_ / 4 + 255) / 256, 256>>>(
        (const float4*)x, (__nv_bfloat162*)xhi, (__nv_bfloat162*)xlo, M_ * E_ / 4);
    conv_split<<<(3 * E_ * E_ / 4 + 255) / 256, 256>>>(
        (const float4*)Wqkv, (__nv_bfloat162*)wqh, (__nv_bfloat162*)wql, 3 * E_ * E_ / 4);
    conv_split<<<(E_ * E_ / 4 + 255) / 256, 256>>>(
        (const float4*)Wout, (__nv_bfloat162*)woh, (__nv_bfloat162*)wol, E_ * E_ / 4);

    // 1) QKV projection -> pre-converted attention operands
    gemm_split<1><<<dim3(3 * E_ / 128, M_ / 128), 256, GEMM_SMEM>>>(
        xhi, xlo, wqh, wql, bqkv, nullptr,
        qhi, qlo, khi, klo, v16, M_, 3 * E_, E_);

    // 2) attention -> split attn output
    attention_tc<<<dim3(L_ / 128, H_, B_), 256, ATTN_SMEM>>>(
        qhi, qlo, khi, klo, v16, ahi, alo);

    // 3) out projection (fp32 epilogue)
    gemm_split<0><<<dim3(E_ / 128, M_ / 128), 256, GEMM_SMEM>>>(
        ahi, alo, woh, wol, bout, out,
        nullptr, nullptr, nullptr, nullptr, nullptr, M_, E_, E_);
}

// round 8
// speedup vs baseline: 3.7835x; 1.2172x over previous
#include <cuda_runtime.h>
#include <cuda_bf16.h>
#include <cuda_fp16.h>
#include <math.h>
#include <stdint.h>

#define B_  2
#define L_  2048
#define E_  1024
#define H_  16
#define HD_ 64
#define M_  (B_ * L_)   // 4096

// ---------------------------------------------------------------------------
// Scratch
// ---------------------------------------------------------------------------
__device__ __align__(16) __nv_bfloat16 g_xhi[M_ * E_];
__device__ __align__(16) __nv_bfloat16 g_xlo[M_ * E_];
__device__ __align__(16) __nv_bfloat16 g_wqkvhi[3 * E_ * E_];
__device__ __align__(16) __nv_bfloat16 g_wqkvlo[3 * E_ * E_];
__device__ __align__(16) __nv_bfloat16 g_wohi[E_ * E_];
__device__ __align__(16) __nv_bfloat16 g_wolo[E_ * E_];
__device__ __align__(16) __half        g_q16h[M_ * E_];  // Q*0.125, fp16 hi
__device__ __align__(16) __half        g_q16l[M_ * E_];  // fp16 residual
__device__ __align__(16) __half        g_k16[M_ * E_];   // K fp16
__device__ __align__(16) __half        g_v16[M_ * E_];   // V fp16
__device__ __align__(16) __nv_bfloat16 g_ahi[M_ * E_];   // attn out, bf16 split
__device__ __align__(16) __nv_bfloat16 g_alo[M_ * E_];

// ---------------------------------------------------------------------------
// helpers
// ---------------------------------------------------------------------------
__device__ __forceinline__ uint32_t smem_to_u32(const void* p) {
    uint32_t a;
    asm("{ .reg .u64 t; cvta.to.shared.u64 t, %1; cvt.u32.u64 %0, t; }" : "=r"(a) : "l"(p));
    return a;
}
__device__ __forceinline__ void cp_async16(uint32_t dst, const void* src) {
    asm volatile("cp.async.cg.shared.global [%0], [%1], 16;" :: "r"(dst), "l"(src));
}
#define CP_COMMIT() asm volatile("cp.async.commit_group;")
#define CP_WAIT1()  asm volatile("cp.async.wait_group 1;")
#define CP_WAIT0()  asm volatile("cp.async.wait_group 0;")

__device__ __forceinline__ void ldmatrix_x4(
    uint32_t& r0, uint32_t& r1, uint32_t& r2, uint32_t& r3, uint32_t addr)
{
    asm volatile("ldmatrix.sync.aligned.m8n8.x4.shared.b16 {%0,%1,%2,%3}, [%4];"
        : "=r"(r0), "=r"(r1), "=r"(r2), "=r"(r3) : "r"(addr));
}
__device__ __forceinline__ void ldmatrix_x4_trans(
    uint32_t& r0, uint32_t& r1, uint32_t& r2, uint32_t& r3, uint32_t addr)
{
    asm volatile("ldmatrix.sync.aligned.m8n8.x4.trans.shared.b16 {%0,%1,%2,%3}, [%4];"
        : "=r"(r0), "=r"(r1), "=r"(r2), "=r"(r3) : "r"(addr));
}
__device__ __forceinline__ void mma_bf16(
    float& c0, float& c1, float& c2, float& c3,
    uint32_t a0, uint32_t a1, uint32_t a2, uint32_t a3, uint32_t b0, uint32_t b1)
{
    asm volatile(
        "mma.sync.aligned.m16n8k16.row.col.f32.bf16.bf16.f32 "
        "{%0,%1,%2,%3}, {%4,%5,%6,%7}, {%8,%9}, {%0,%1,%2,%3};"
        : "+f"(c0), "+f"(c1), "+f"(c2), "+f"(c3)
        : "r"(a0), "r"(a1), "r"(a2), "r"(a3), "r"(b0), "r"(b1));
}
__device__ __forceinline__ void mma_f16(
    float& c0, float& c1, float& c2, float& c3,
    uint32_t a0, uint32_t a1, uint32_t a2, uint32_t a3, uint32_t b0, uint32_t b1)
{
    asm volatile(
        "mma.sync.aligned.m16n8k16.row.col.f32.f16.f16.f32 "
        "{%0,%1,%2,%3}, {%4,%5,%6,%7}, {%8,%9}, {%0,%1,%2,%3};"
        : "+f"(c0), "+f"(c1), "+f"(c2), "+f"(c3)
        : "r"(a0), "r"(a1), "r"(a2), "r"(a3), "r"(b0), "r"(b1));
}
__device__ __forceinline__ uint32_t pack_h2(float a, float b) {
    __half2 p = __floats2half2_rn(a, b);
    return *(uint32_t*)&p;
}
__device__ __forceinline__ void store_split2_bf(
    __nv_bfloat16* hi, __nv_bfloat16* lo, size_t idx, float a, float b)
{
    __nv_bfloat16 ha = __float2bfloat16(a);
    __nv_bfloat16 hb = __float2bfloat16(b);
    *(__nv_bfloat162*)(hi + idx) = __nv_bfloat162(ha, hb);
    *(__nv_bfloat162*)(lo + idx) = __nv_bfloat162(
        __float2bfloat16(a - __bfloat162float(ha)),
        __float2bfloat16(b - __bfloat162float(hb)));
}
__device__ __forceinline__ void store_split2_h(
    __half* hi, __half* lo, size_t idx, float a, float b)
{
    __half ha = __float2half_rn(a);
    __half hb = __float2half_rn(b);
    *(__half2*)(hi + idx) = __half2(ha, hb);
    *(__half2*)(lo + idx) = __floats2half2_rn(a - __half2float(ha),
                                              b - __half2float(hb));
}

// ---------------------------------------------------------------------------
// Prepass: fp32 -> (hi, lo) bf16
// ---------------------------------------------------------------------------
__global__ void conv_split(const float4* __restrict__ src,
                           __nv_bfloat162* __restrict__ hi,
                           __nv_bfloat162* __restrict__ lo, int n4)
{
    int i = blockIdx.x * blockDim.x + threadIdx.x;
    if (i >= n4) return;
    float4 t = src[i];
    __nv_bfloat16 h0 = __float2bfloat16(t.x);
    __nv_bfloat16 h1 = __float2bfloat16(t.y);
    __nv_bfloat16 h2 = __float2bfloat16(t.z);
    __nv_bfloat16 h3 = __float2bfloat16(t.w);
    hi[2*i]   = __nv_bfloat162(h0, h1);
    hi[2*i+1] = __nv_bfloat162(h2, h3);
    lo[2*i]   = __nv_bfloat162(__float2bfloat16(t.x - __bfloat162float(h0)),
                               __float2bfloat16(t.y - __bfloat162float(h1)));
    lo[2*i+1] = __nv_bfloat162(__float2bfloat16(t.z - __bfloat162float(h2)),
                               __float2bfloat16(t.w - __bfloat162float(h3)));
}

// ---------------------------------------------------------------------------
// GEMM on pre-split bf16 (unchanged structure from R7; passing @ ~303us)
// EPI=0: fp32+bias -> Cf. EPI=1: qkv epilogue -> fp16 attention operands.
// ---------------------------------------------------------------------------
#define GT_STRIDE 40
#define GT_TILE   (128 * GT_STRIDE * 2)   // 10240 B
#define GT_STAGE  (4 * GT_TILE)           // 40960 B
#define GEMM_SMEM (2 * GT_STAGE)          // 81920 B

template<int EPI>
__global__ __launch_bounds__(256, 2) void gemm_split(
    const __nv_bfloat16* __restrict__ Ahi, const __nv_bfloat16* __restrict__ Alo,
    const __nv_bfloat16* __restrict__ Bhi, const __nv_bfloat16* __restrict__ Blo,
    const float* __restrict__ bias, float* __restrict__ Cf,
    __half* __restrict__ q16h, __half* __restrict__ q16l,
    __half* __restrict__ k16, __half* __restrict__ v16,
    int M, int N, int K)
{
    extern __shared__ char smg[];
    const uint32_t sbase = smem_to_u32(smg);

    const int bm   = blockIdx.y * 128;
    const int bn   = blockIdx.x * 128;
    const int tid  = threadIdx.x;
    const int wid  = tid >> 5;
    const int lane = tid & 31;
    const int wm   = wid >> 2;
    const int wn   = wid & 3;

    float c[4][4][4];
#pragma unroll
    for (int i = 0; i < 4; i++)
#pragma unroll
        for (int j = 0; j < 4; j++)
#pragma unroll
            for (int r = 0; r < 4; r++) c[i][j][r] = 0.f;

    auto load_stage = [&](int s, int k0) {
        const uint32_t base = sbase + s * GT_STAGE;
        const __nv_bfloat16* srcs[4] = {
            Ahi + (size_t)bm * K + k0, Alo + (size_t)bm * K + k0,
            Bhi + (size_t)bn * K + k0, Blo + (size_t)bn * K + k0 };
#pragma unroll
        for (int t = 0; t < 4; t++) {
#pragma unroll
            for (int i = 0; i < 2; i++) {
                int chunk = tid * 2 + i;
                int row   = chunk >> 2;
                int cc    = chunk & 3;
                cp_async16(base + t * GT_TILE + row * (GT_STRIDE * 2) + cc * 16,
                           srcs[t] + (size_t)row * K + cc * 8);
            }
        }
    };

    load_stage(0, 0);
    CP_COMMIT();

    const int niter = K / 32;
    for (int it = 0; it < niter; it++) {
        if (it + 1 < niter) { load_stage((it + 1) & 1, (it + 1) * 32); CP_COMMIT(); CP_WAIT1(); }
        else                { CP_WAIT0(); }
        __syncthreads();

        const uint32_t stage = sbase + (it & 1) * GT_STAGE;
#pragma unroll
        for (int ks = 0; ks < 2; ks++) {
            const int kof = ks * 16;
            uint32_t ahi[4][4], alo[4][4], bhi[4][2], blo[4][2];
#pragma unroll
            for (int i = 0; i < 4; i++) {
                int m0 = wm * 64 + i * 16;
                uint32_t ad = stage +
                    (uint32_t)((m0 + (lane & 15)) * GT_STRIDE + kof + (lane >> 4) * 8) * 2;
                ldmatrix_x4(ahi[i][0], ahi[i][1], ahi[i][2], ahi[i][3], ad);
                ldmatrix_x4(alo[i][0], alo[i][1], alo[i][2], alo[i][3], ad + GT_TILE);
            }
#pragma unroll
            for (int jp = 0; jp < 2; jp++) {
                int n0 = wn * 32 + jp * 16;
                int nrow = n0 + ((lane >> 4) << 3) + (lane & 7);
                int bk   = kof + (((lane >> 3) & 1) << 3);
                uint32_t bd = stage + 2 * GT_TILE + (uint32_t)(nrow * GT_STRIDE + bk) * 2;
                ldmatrix_x4(bhi[jp*2][0], bhi[jp*2][1], bhi[jp*2+1][0], bhi[jp*2+1][1], bd);
                ldmatrix_x4(blo[jp*2][0], blo[jp*2][1], blo[jp*2+1][0], blo[jp*2+1][1],
                            bd + GT_TILE);
            }
#pragma unroll
            for (int i = 0; i < 4; i++)
#pragma unroll
                for (int j = 0; j < 4; j++) {
                    mma_bf16(c[i][j][0], c[i][j][1], c[i][j][2], c[i][j][3],
                             ahi[i][0], ahi[i][1], ahi[i][2], ahi[i][3],
                             bhi[j][0], bhi[j][1]);
                    mma_bf16(c[i][j][0], c[i][j][1], c[i][j][2], c[i][j][3],
                             ahi[i][0], ahi[i][1], ahi[i][2], ahi[i][3],
                             blo[j][0], blo[j][1]);
                    mma_bf16(c[i][j][0], c[i][j][1], c[i][j][2], c[i][j][3],
                             alo[i][0], alo[i][1], alo[i][2], alo[i][3],
                             bhi[j][0], bhi[j][1]);
                }
        }
        __syncthreads();
    }

    // ---- epilogue ----
    const int g4 = lane >> 2;
    const int t4 = lane & 3;
    if (EPI == 0) {
#pragma unroll
        for (int i = 0; i < 4; i++) {
            int row0 = bm + wm * 64 + i * 16 + g4;
#pragma unroll
            for (int j = 0; j < 4; j++) {
                int col = bn + wn * 32 + j * 8 + t4 * 2;
                float bx = bias[col], by = bias[col + 1];
                *(float2*)(Cf + (size_t)row0 * N + col) =
                    make_float2(c[i][j][0] + bx, c[i][j][1] + by);
                *(float2*)(Cf + (size_t)(row0 + 8) * N + col) =
                    make_float2(c[i][j][2] + bx, c[i][j][3] + by);
            }
        }
    } else {
        const int seg     = bn >> 10;          // 0=Q, 1=K, 2=V
        const int segbase = bn & 1023;
#pragma unroll
        for (int i = 0; i < 4; i++) {
            int row0 = bm + wm * 64 + i * 16 + g4;
#pragma unroll
            for (int j = 0; j < 4; j++) {
                int colg = bn + wn * 32 + j * 8 + t4 * 2;
                int cols = segbase + wn * 32 + j * 8 + t4 * 2;
                float bx = bias[colg], by = bias[colg + 1];
                float v0 = c[i][j][0] + bx, v1 = c[i][j][1] + by;
                float v2 = c[i][j][2] + bx, v3 = c[i][j][3] + by;
                size_t i0 = (size_t)row0 * E_ + cols;
                size_t i1 = (size_t)(row0 + 8) * E_ + cols;
                if (seg == 0) {
                    store_split2_h(q16h, q16l, i0, v0 * 0.125f, v1 * 0.125f);
                    store_split2_h(q16h, q16l, i1, v2 * 0.125f, v3 * 0.125f);
                } else if (seg == 1) {
                    *(__half2*)(k16 + i0) = __floats2half2_rn(v0, v1);
                    *(__half2*)(k16 + i1) = __floats2half2_rn(v2, v3);
                } else {
                    *(__half2*)(v16 + i0) = __floats2half2_rn(v0, v1);
                    *(__half2*)(v16 + i1) = __floats2half2_rn(v2, v3);
                }
            }
        }
    }
}

// ---------------------------------------------------------------------------
// Flash attention, all-fp16 MMA path (3 MMA units/tile-col vs 5 before):
// S = (Qh + Ql) @ K16^T  (2 fp16 mmas);  O += P16 @ V16  (1 fp16 mma).
// Block: (b, h, 128 q-rows). K-tiles of 64. cp.async double buffer (K,V).
// ---------------------------------------------------------------------------
#define AT_STRIDE 72
#define AT_TILE   (64 * AT_STRIDE * 2)     // 9216
#define AT_STAGE  (2 * AT_TILE)            // 18432 (K16, V16)
#define ATTN_SMEM (2 * AT_STAGE)           // 36864

__global__ __launch_bounds__(256) void attention_tc(
    const __half* __restrict__ qh, const __half* __restrict__ ql,
    const __half* __restrict__ k16, const __half* __restrict__ v16,
    __nv_bfloat16* __restrict__ ahi, __nv_bfloat16* __restrict__ alo)
{
    extern __shared__ char sma[];
    const uint32_t sbase = smem_to_u32(sma);

    const int q0   = blockIdx.x * 128;
    const int h    = blockIdx.y;
    const int b    = blockIdx.z;
    const int tid  = threadIdx.x;
    const int wid  = tid >> 5;
    const int lane = tid & 31;
    const int basecol = h * HD_;

    // ---- Q fragments directly from global (ldmatrix A-frag layout) ----
    uint32_t qfh[4][4], qfl[4][4];
    {
        const int r0 = b * L_ + q0 + wid * 16 + (lane >> 2);
        const int c0 = basecol + (lane & 3) * 2;
#pragma unroll
        for (int ks = 0; ks < 4; ks++) {
            size_t i00 = (size_t)r0 * E_ + c0 + ks * 16;
            qfh[ks][0] = *(const uint32_t*)(qh + i00);
            qfh[ks][1] = *(const uint32_t*)(qh + i00 + 8 * E_);
            qfh[ks][2] = *(const uint32_t*)(qh + i00 + 8);
            qfh[ks][3] = *(const uint32_t*)(qh + i00 + 8 * E_ + 8);
            qfl[ks][0] = *(const uint32_t*)(ql + i00);
            qfl[ks][1] = *(const uint32_t*)(ql + i00 + 8 * E_);
            qfl[ks][2] = *(const uint32_t*)(ql + i00 + 8);
            qfl[ks][3] = *(const uint32_t*)(ql + i00 + 8 * E_ + 8);
        }
    }

    auto load_kv = [&](int s, int kt) {
        const uint32_t base = sbase + s * AT_STAGE;
        const int rowg = b * L_ + kt;
#pragma unroll
        for (int i = 0; i < 2; i++) {
            int chunk = tid * 2 + i;        // 0..511
            int row   = chunk >> 3;
            int cc    = chunk & 7;
            size_t src = (size_t)(rowg + row) * E_ + basecol + cc * 8;
            uint32_t doff = row * (AT_STRIDE * 2) + cc * 16;
            cp_async16(base + doff,           k16 + src);
            cp_async16(base + AT_TILE + doff, v16 + src);
        }
    };

    load_kv(0, 0);
    CP_COMMIT();

    float o[8][4];
#pragma unroll
    for (int j = 0; j < 8; j++)
#pragma unroll
        for (int r = 0; r < 4; r++) o[j][r] = 0.f;
    float m0 = -1e30f, m1 = -1e30f, l0 = 0.f, l1 = 0.f;

    const int NTILE = L_ / 64;
    for (int it = 0; it < NTILE; it++) {
        if (it + 1 < NTILE) { load_kv((it + 1) & 1, (it + 1) * 64); CP_COMMIT(); CP_WAIT1(); }
        else                { CP_WAIT0(); }
        __syncthreads();

        const uint32_t stage = sbase + (it & 1) * AT_STAGE;

        // ---- S = (Qh + Ql) @ K^T, fp16 ----
        float s[8][4];
#pragma unroll
        for (int j = 0; j < 8; j++)
#pragma unroll
            for (int r = 0; r < 4; r++) s[j][r] = 0.f;

#pragma unroll
        for (int ks = 0; ks < 4; ks++) {
            const int kof = ks * 16;
            uint32_t kf[8][2];
#pragma unroll
            for (int jp = 0; jp < 4; jp++) {
                int nrow = jp * 16 + ((lane >> 4) << 3) + (lane & 7);
                int bk   = kof + (((lane >> 3) & 1) << 3);
                uint32_t bd = stage + (uint32_t)(nrow * AT_STRIDE + bk) * 2;
                ldmatrix_x4(kf[jp*2][0], kf[jp*2][1], kf[jp*2+1][0], kf[jp*2+1][1], bd);
            }
#pragma unroll
            for (int j = 0; j < 8; j++) {
                mma_f16(s[j][0], s[j][1], s[j][2], s[j][3],
                        qfh[ks][0], qfh[ks][1], qfh[ks][2], qfh[ks][3],
                        kf[j][0], kf[j][1]);
                mma_f16(s[j][0], s[j][1], s[j][2], s[j][3],
                        qfl[ks][0], qfl[ks][1], qfl[ks][2], qfl[ks][3],
                        kf[j][0], kf[j][1]);
            }
        }

        // ---- online softmax ----
        float rm0 = -1e30f, rm1 = -1e30f;
#pragma unroll
        for (int j = 0; j < 8; j++) {
            rm0 = fmaxf(rm0, fmaxf(s[j][0], s[j][1]));
            rm1 = fmaxf(rm1, fmaxf(s[j][2], s[j][3]));
        }
        rm0 = fmaxf(rm0, __shfl_xor_sync(0xffffffffu, rm0, 1));
        rm0 = fmaxf(rm0, __shfl_xor_sync(0xffffffffu, rm0, 2));
        rm1 = fmaxf(rm1, __shfl_xor_sync(0xffffffffu, rm1, 1));
        rm1 = fmaxf(rm1, __shfl_xor_sync(0xffffffffu, rm1, 2));

        float nm0 = fmaxf(m0, rm0), nm1 = fmaxf(m1, rm1);
        float a0 = __expf(m0 - nm0), a1 = __expf(m1 - nm1);

        float rs0 = 0.f, rs1 = 0.f;
#pragma unroll
        for (int j = 0; j < 8; j++) {
            s[j][0] = __expf(s[j][0] - nm0);
            s[j][1] = __expf(s[j][1] - nm0);
            s[j][2] = __expf(s[j][2] - nm1);
            s[j][3] = __expf(s[j][3] - nm1);
            rs0 += s[j][0] + s[j][1];
            rs1 += s[j][2] + s[j][3];
        }
        rs0 += __shfl_xor_sync(0xffffffffu, rs0, 1);
        rs0 += __shfl_xor_sync(0xffffffffu, rs0, 2);
        rs1 += __shfl_xor_sync(0xffffffffu, rs1, 1);
        rs1 += __shfl_xor_sync(0xffffffffu, rs1, 2);

        l0 = l0 * a0 + rs0;  m0 = nm0;
        l1 = l1 * a1 + rs1;  m1 = nm1;

#pragma unroll
        for (int j = 0; j < 8; j++) {
            o[j][0] *= a0; o[j][1] *= a0;
            o[j][2] *= a1; o[j][3] *= a1;
        }

        // ---- O += P @ V (single fp16 P) ----
#pragma unroll
        for (int kk = 0; kk < 4; kk++) {
            uint32_t ph0 = pack_h2(s[2*kk][0],   s[2*kk][1]);
            uint32_t ph1 = pack_h2(s[2*kk][2],   s[2*kk][3]);
            uint32_t ph2 = pack_h2(s[2*kk+1][0], s[2*kk+1][1]);
            uint32_t ph3 = pack_h2(s[2*kk+1][2], s[2*kk+1][3]);
#pragma unroll
            for (int jp = 0; jp < 4; jp++) {
                int vrow = kk * 16 + (((lane >> 3) & 1) << 3) + (lane & 7);
                int vcol = jp * 16 + ((lane >> 4) << 3);
                uint32_t vd = stage + AT_TILE + (uint32_t)(vrow * AT_STRIDE + vcol) * 2;
                uint32_t v0, v1, v2, v3;
                ldmatrix_x4_trans(v0, v1, v2, v3, vd);
                mma_f16(o[jp*2][0],   o[jp*2][1],   o[jp*2][2],   o[jp*2][3],
                        ph0, ph1, ph2, ph3, v0, v1);
                mma_f16(o[jp*2+1][0], o[jp*2+1][1], o[jp*2+1][2], o[jp*2+1][3],
                        ph0, ph1, ph2, ph3, v2, v3);
            }
        }
        __syncthreads();
    }

    // ---- normalize + split-write for out-GEMM ----
    float inv0 = 1.f / l0, inv1 = 1.f / l1;
    const int orow = b * L_ + q0 + wid * 16 + (lane >> 2);
#pragma unroll
    for (int j = 0; j < 8; j++) {
        int col = basecol + j * 8 + (lane & 3) * 2;
        store_split2_bf(ahi, alo, (size_t)orow * E_ + col,       o[j][0] * inv0, o[j][1] * inv0);
        store_split2_bf(ahi, alo, (size_t)(orow + 8) * E_ + col, o[j][2] * inv1, o[j][3] * inv1);
    }
}

// ---------------------------------------------------------------------------
extern "C" void kernel_launch(void* const* d_in, const int* in_sizes, int n_in,
                              void* d_out, int out_size)
{
    const float* x    = (const float*)d_in[0];
    const float* Wqkv = (const float*)d_in[1];
    const float* bqkv = (const float*)d_in[2];
    const float* Wout = (const float*)d_in[3];
    const float* bout = (const float*)d_in[4];
    float* out = (float*)d_out;

    __nv_bfloat16 *xhi, *xlo, *wqh, *wql, *woh, *wol, *ahi, *alo;
    __half *q16h, *q16l, *k16, *v16;
    cudaGetSymbolAddress((void**)&xhi, g_xhi);    cudaGetSymbolAddress((void**)&xlo, g_xlo);
    cudaGetSymbolAddress((void**)&wqh, g_wqkvhi); cudaGetSymbolAddress((void**)&wql, g_wqkvlo);
    cudaGetSymbolAddress((void**)&woh, g_wohi);   cudaGetSymbolAddress((void**)&wol, g_wolo);
    cudaGetSymbolAddress((void**)&q16h, g_q16h);  cudaGetSymbolAddress((void**)&q16l, g_q16l);
    cudaGetSymbolAddress((void**)&k16, g_k16);    cudaGetSymbolAddress((void**)&v16, g_v16);
    cudaGetSymbolAddress((void**)&ahi, g_ahi);    cudaGetSymbolAddress((void**)&alo, g_alo);

    static int attr_done = 0;
    if (!attr_done) {
        cudaFuncSetAttribute(gemm_split<0>,
                             cudaFuncAttributeMaxDynamicSharedMemorySize, GEMM_SMEM);
        cudaFuncSetAttribute(gemm_split<1>,
                             cudaFuncAttributeMaxDynamicSharedMemorySize, GEMM_SMEM);
        cudaFuncSetAttribute(attention_tc,
                             cudaFuncAttributeMaxDynamicSharedMemorySize, ATTN_SMEM);
        attr_done = 1;
    }

    // 0) prepass splits
    conv_split<<<(M_ * E_ / 4 + 255) / 256, 256>>>(
        (const float4*)x, (__nv_bfloat162*)xhi, (__nv_bfloat162*)xlo, M_ * E_ / 4);
    conv_split<<<(3 * E_ * E_ / 4 + 255) / 256, 256>>>(
        (const float4*)Wqkv, (__nv_bfloat162*)wqh, (__nv_bfloat162*)wql, 3 * E_ * E_ / 4);
    conv_split<<<(E_ * E_ / 4 + 255) / 256, 256>>>(
        (const float4*)Wout, (__nv_bfloat162*)woh, (__nv_bfloat162*)wol, E_ * E_ / 4);

    // 1) QKV projection -> fp16 attention operands
    gemm_split<1><<<dim3(3 * E_ / 128, M_ / 128), 256, GEMM_SMEM>>>(
        xhi, xlo, wqh, wql, bqkv, nullptr,
        q16h, q16l, k16, v16, M_, 3 * E_, E_);

    // 2) attention -> split attn output
    attention_tc<<<dim3(L_ / 128, H_, B_), 256, ATTN_SMEM>>>(
        q16h, q16l, k16, v16, ahi, alo);

    // 3) out projection (fp32 epilogue)
    gemm_split<0><<<dim3(E_ / 128, M_ / 128), 256, GEMM_SMEM>>>(
        ahi, alo, woh, wol, bout, out,
        nullptr, nullptr, nullptr, nullptr, M_, E_, E_);
}

// round 9
// speedup vs baseline: 4.6218x; 1.2216x over previous
#include <cuda_runtime.h>
#include <cuda_bf16.h>
#include <cuda_fp16.h>
#include <math.h>
#include <stdint.h>

#define B_  2
#define L_  2048
#define E_  1024
#define H_  16
#define HD_ 64
#define M_  (B_ * L_)   // 4096

// ---------------------------------------------------------------------------
// Scratch (fp16 world)
// ---------------------------------------------------------------------------
__device__ __align__(16) __half g_xh[M_ * E_];        // x fp16 hi
__device__ __align__(16) __half g_xl[M_ * E_];        // x fp16 residual
__device__ __align__(16) __half g_wqkv16[3 * E_ * E_];// Wqkv fp16
__device__ __align__(16) __half g_wo16[E_ * E_];      // Wout fp16
__device__ __align__(16) __half g_q16h[M_ * E_];      // Q*0.125 fp16 hi
__device__ __align__(16) __half g_q16l[M_ * E_];      // fp16 residual
__device__ __align__(16) __half g_k16[M_ * E_];       // K fp16
__device__ __align__(16) __half g_v16[M_ * E_];       // V fp16
__device__ __align__(16) __half g_ah[M_ * E_];        // attn out fp16 hi
__device__ __align__(16) __half g_al[M_ * E_];        // attn out fp16 residual

// ---------------------------------------------------------------------------
// helpers
// ---------------------------------------------------------------------------
__device__ __forceinline__ uint32_t smem_to_u32(const void* p) {
    uint32_t a;
    asm("{ .reg .u64 t; cvta.to.shared.u64 t, %1; cvt.u32.u64 %0, t; }" : "=r"(a) : "l"(p));
    return a;
}
__device__ __forceinline__ void cp_async16(uint32_t dst, const void* src) {
    asm volatile("cp.async.cg.shared.global [%0], [%1], 16;" :: "r"(dst), "l"(src));
}
#define CP_COMMIT() asm volatile("cp.async.commit_group;")
#define CP_WAIT1()  asm volatile("cp.async.wait_group 1;")
#define CP_WAIT0()  asm volatile("cp.async.wait_group 0;")

__device__ __forceinline__ void ldmatrix_x4(
    uint32_t& r0, uint32_t& r1, uint32_t& r2, uint32_t& r3, uint32_t addr)
{
    asm volatile("ldmatrix.sync.aligned.m8n8.x4.shared.b16 {%0,%1,%2,%3}, [%4];"
        : "=r"(r0), "=r"(r1), "=r"(r2), "=r"(r3) : "r"(addr));
}
__device__ __forceinline__ void ldmatrix_x4_trans(
    uint32_t& r0, uint32_t& r1, uint32_t& r2, uint32_t& r3, uint32_t addr)
{
    asm volatile("ldmatrix.sync.aligned.m8n8.x4.trans.shared.b16 {%0,%1,%2,%3}, [%4];"
        : "=r"(r0), "=r"(r1), "=r"(r2), "=r"(r3) : "r"(addr));
}
__device__ __forceinline__ void mma_f16(
    float& c0, float& c1, float& c2, float& c3,
    uint32_t a0, uint32_t a1, uint32_t a2, uint32_t a3, uint32_t b0, uint32_t b1)
{
    asm volatile(
        "mma.sync.aligned.m16n8k16.row.col.f32.f16.f16.f32 "
        "{%0,%1,%2,%3}, {%4,%5,%6,%7}, {%8,%9}, {%0,%1,%2,%3};"
        : "+f"(c0), "+f"(c1), "+f"(c2), "+f"(c3)
        : "r"(a0), "r"(a1), "r"(a2), "r"(a3), "r"(b0), "r"(b1));
}
__device__ __forceinline__ uint32_t pack_h2(float a, float b) {
    __half2 p = __floats2half2_rn(a, b);
    return *(uint32_t*)&p;
}
__device__ __forceinline__ void store_split2_h(
    __half* hi, __half* lo, size_t idx, float a, float b)
{
    __half ha = __float2half_rn(a);
    __half hb = __float2half_rn(b);
    *(__half2*)(hi + idx) = __half2(ha, hb);
    *(__half2*)(lo + idx) = __floats2half2_rn(a - __half2float(ha),
                                              b - __half2float(hb));
}

// ---------------------------------------------------------------------------
// Prepass kernels
// ---------------------------------------------------------------------------
__global__ void conv_split_h(const float4* __restrict__ src,
                             __half2* __restrict__ hi,
                             __half2* __restrict__ lo, int n4)
{
    int i = blockIdx.x * blockDim.x + threadIdx.x;
    if (i >= n4) return;
    float4 t = src[i];
    __half h0 = __float2half_rn(t.x);
    __half h1 = __float2half_rn(t.y);
    __half h2 = __float2half_rn(t.z);
    __half h3 = __float2half_rn(t.w);
    hi[2*i]   = __half2(h0, h1);
    hi[2*i+1] = __half2(h2, h3);
    lo[2*i]   = __floats2half2_rn(t.x - __half2float(h0), t.y - __half2float(h1));
    lo[2*i+1] = __floats2half2_rn(t.z - __half2float(h2), t.w - __half2float(h3));
}

__global__ void conv_h(const float4* __restrict__ src,
                       __half2* __restrict__ dst, int n4)
{
    int i = blockIdx.x * blockDim.x + threadIdx.x;
    if (i >= n4) return;
    float4 t = src[i];
    dst[2*i]   = __floats2half2_rn(t.x, t.y);
    dst[2*i+1] = __floats2half2_rn(t.z, t.w);
}

// ---------------------------------------------------------------------------
// GEMM: C = (Ah + Al) @ Wh^T (+bias) — 2 fp16 MMAs per tile-atom.
// BM=128, BN=128, BK=32; 256 threads, 8 warps. cp.async double-buffered.
// Stage tiles: Ah, Al, Wh (3 x 10240 B).
// EPI=0: fp32+bias -> Cf. EPI=1: qkv epilogue -> fp16 attention operands.
// ---------------------------------------------------------------------------
#define GT_STRIDE 40
#define GT_TILE   (128 * GT_STRIDE * 2)   // 10240 B
#define GT_STAGE  (3 * GT_TILE)           // 30720 B
#define GEMM_SMEM (2 * GT_STAGE)          // 61440 B

template<int EPI>
__global__ __launch_bounds__(256, 2) void gemm_split(
    const __half* __restrict__ Ahi, const __half* __restrict__ Alo,
    const __half* __restrict__ Wh,
    const float* __restrict__ bias, float* __restrict__ Cf,
    __half* __restrict__ q16h, __half* __restrict__ q16l,
    __half* __restrict__ k16, __half* __restrict__ v16,
    int M, int N, int K)
{
    extern __shared__ char smg[];
    const uint32_t sbase = smem_to_u32(smg);

    const int bm   = blockIdx.y * 128;
    const int bn   = blockIdx.x * 128;
    const int tid  = threadIdx.x;
    const int wid  = tid >> 5;
    const int lane = tid & 31;
    const int wm   = wid >> 2;
    const int wn   = wid & 3;

    float c[4][4][4];
#pragma unroll
    for (int i = 0; i < 4; i++)
#pragma unroll
        for (int j = 0; j < 4; j++)
#pragma unroll
            for (int r = 0; r < 4; r++) c[i][j][r] = 0.f;

    auto load_stage = [&](int s, int k0) {
        const uint32_t base = sbase + s * GT_STAGE;
        const __half* srcs[3] = {
            Ahi + (size_t)bm * K + k0, Alo + (size_t)bm * K + k0,
            Wh  + (size_t)bn * K + k0 };
#pragma unroll
        for (int t = 0; t < 3; t++) {
#pragma unroll
            for (int i = 0; i < 2; i++) {
                int chunk = tid * 2 + i;        // 0..511
                int row   = chunk >> 2;
                int cc    = chunk & 3;
                cp_async16(base + t * GT_TILE + row * (GT_STRIDE * 2) + cc * 16,
                           srcs[t] + (size_t)row * K + cc * 8);
            }
        }
    };

    load_stage(0, 0);
    CP_COMMIT();

    const int niter = K / 32;
    for (int it = 0; it < niter; it++) {
        if (it + 1 < niter) { load_stage((it + 1) & 1, (it + 1) * 32); CP_COMMIT(); CP_WAIT1(); }
        else                { CP_WAIT0(); }
        __syncthreads();

        const uint32_t stage = sbase + (it & 1) * GT_STAGE;
#pragma unroll
        for (int ks = 0; ks < 2; ks++) {
            const int kof = ks * 16;
            uint32_t ahi[4][4], alo[4][4], bfr[4][2];
#pragma unroll
            for (int i = 0; i < 4; i++) {
                int m0 = wm * 64 + i * 16;
                uint32_t ad = stage +
                    (uint32_t)((m0 + (lane & 15)) * GT_STRIDE + kof + (lane >> 4) * 8) * 2;
                ldmatrix_x4(ahi[i][0], ahi[i][1], ahi[i][2], ahi[i][3], ad);
                ldmatrix_x4(alo[i][0], alo[i][1], alo[i][2], alo[i][3], ad + GT_TILE);
            }
#pragma unroll
            for (int jp = 0; jp < 2; jp++) {
                int n0 = wn * 32 + jp * 16;
                int nrow = n0 + ((lane >> 4) << 3) + (lane & 7);
                int bk   = kof + (((lane >> 3) & 1) << 3);
                uint32_t bd = stage + 2 * GT_TILE + (uint32_t)(nrow * GT_STRIDE + bk) * 2;
                ldmatrix_x4(bfr[jp*2][0], bfr[jp*2][1], bfr[jp*2+1][0], bfr[jp*2+1][1], bd);
            }
#pragma unroll
            for (int i = 0; i < 4; i++)
#pragma unroll
                for (int j = 0; j < 4; j++) {
                    mma_f16(c[i][j][0], c[i][j][1], c[i][j][2], c[i][j][3],
                            ahi[i][0], ahi[i][1], ahi[i][2], ahi[i][3],
                            bfr[j][0], bfr[j][1]);
                    mma_f16(c[i][j][0], c[i][j][1], c[i][j][2], c[i][j][3],
                            alo[i][0], alo[i][1], alo[i][2], alo[i][3],
                            bfr[j][0], bfr[j][1]);
                }
        }
        __syncthreads();
    }

    // ---- epilogue ----
    const int g4 = lane >> 2;
    const int t4 = lane & 3;
    if (EPI == 0) {
#pragma unroll
        for (int i = 0; i < 4; i++) {
            int row0 = bm + wm * 64 + i * 16 + g4;
#pragma unroll
            for (int j = 0; j < 4; j++) {
                int col = bn + wn * 32 + j * 8 + t4 * 2;
                float bx = bias[col], by = bias[col + 1];
                *(float2*)(Cf + (size_t)row0 * N + col) =
                    make_float2(c[i][j][0] + bx, c[i][j][1] + by);
                *(float2*)(Cf + (size_t)(row0 + 8) * N + col) =
                    make_float2(c[i][j][2] + bx, c[i][j][3] + by);
            }
        }
    } else {
        const int seg     = bn >> 10;          // 0=Q, 1=K, 2=V
        const int segbase = bn & 1023;
#pragma unroll
        for (int i = 0; i < 4; i++) {
            int row0 = bm + wm * 64 + i * 16 + g4;
#pragma unroll
            for (int j = 0; j < 4; j++) {
                int colg = bn + wn * 32 + j * 8 + t4 * 2;
                int cols = segbase + wn * 32 + j * 8 + t4 * 2;
                float bx = bias[colg], by = bias[colg + 1];
                float v0 = c[i][j][0] + bx, v1 = c[i][j][1] + by;
                float v2 = c[i][j][2] + bx, v3 = c[i][j][3] + by;
                size_t i0 = (size_t)row0 * E_ + cols;
                size_t i1 = (size_t)(row0 + 8) * E_ + cols;
                if (seg == 0) {
                    store_split2_h(q16h, q16l, i0, v0 * 0.125f, v1 * 0.125f);
                    store_split2_h(q16h, q16l, i1, v2 * 0.125f, v3 * 0.125f);
                } else if (seg == 1) {
                    *(__half2*)(k16 + i0) = __floats2half2_rn(v0, v1);
                    *(__half2*)(k16 + i1) = __floats2half2_rn(v2, v3);
                } else {
                    *(__half2*)(v16 + i0) = __floats2half2_rn(v0, v1);
                    *(__half2*)(v16 + i1) = __floats2half2_rn(v2, v3);
                }
            }
        }
    }
}

// ---------------------------------------------------------------------------
// Flash attention (unchanged math from R8, fp16 split output).
// ---------------------------------------------------------------------------
#define AT_STRIDE 72
#define AT_TILE   (64 * AT_STRIDE * 2)     // 9216
#define AT_STAGE  (2 * AT_TILE)            // 18432 (K16, V16)
#define ATTN_SMEM (2 * AT_STAGE)           // 36864

__global__ __launch_bounds__(256) void attention_tc(
    const __half* __restrict__ qh, const __half* __restrict__ ql,
    const __half* __restrict__ k16, const __half* __restrict__ v16,
    __half* __restrict__ ah, __half* __restrict__ al)
{
    extern __shared__ char sma[];
    const uint32_t sbase = smem_to_u32(sma);

    const int q0   = blockIdx.x * 128;
    const int h    = blockIdx.y;
    const int b    = blockIdx.z;
    const int tid  = threadIdx.x;
    const int wid  = tid >> 5;
    const int lane = tid & 31;
    const int basecol = h * HD_;

    // ---- Q fragments directly from global (ldmatrix A-frag layout) ----
    uint32_t qfh[4][4], qfl[4][4];
    {
        const int r0 = b * L_ + q0 + wid * 16 + (lane >> 2);
        const int c0 = basecol + (lane & 3) * 2;
#pragma unroll
        for (int ks = 0; ks < 4; ks++) {
            size_t i00 = (size_t)r0 * E_ + c0 + ks * 16;
            qfh[ks][0] = *(const uint32_t*)(qh + i00);
            qfh[ks][1] = *(const uint32_t*)(qh + i00 + 8 * E_);
            qfh[ks][2] = *(const uint32_t*)(qh + i00 + 8);
            qfh[ks][3] = *(const uint32_t*)(qh + i00 + 8 * E_ + 8);
            qfl[ks][0] = *(const uint32_t*)(ql + i00);
            qfl[ks][1] = *(const uint32_t*)(ql + i00 + 8 * E_);
            qfl[ks][2] = *(const uint32_t*)(ql + i00 + 8);
            qfl[ks][3] = *(const uint32_t*)(ql + i00 + 8 * E_ + 8);
        }
    }

    auto load_kv = [&](int s, int kt) {
        const uint32_t base = sbase + s * AT_STAGE;
        const int rowg = b * L_ + kt;
#pragma unroll
        for (int i = 0; i < 2; i++) {
            int chunk = tid * 2 + i;        // 0..511
            int row   = chunk >> 3;
            int cc    = chunk & 7;
            size_t src = (size_t)(rowg + row) * E_ + basecol + cc * 8;
            uint32_t doff = row * (AT_STRIDE * 2) + cc * 16;
            cp_async16(base + doff,           k16 + src);
            cp_async16(base + AT_TILE + doff, v16 + src);
        }
    };

    load_kv(0, 0);
    CP_COMMIT();

    float o[8][4];
#pragma unroll
    for (int j = 0; j < 8; j++)
#pragma unroll
        for (int r = 0; r < 4; r++) o[j][r] = 0.f;
    float m0 = -1e30f, m1 = -1e30f, l0 = 0.f, l1 = 0.f;

    const int NTILE = L_ / 64;
    for (int it = 0; it < NTILE; it++) {
        if (it + 1 < NTILE) { load_kv((it + 1) & 1, (it + 1) * 64); CP_COMMIT(); CP_WAIT1(); }
        else                { CP_WAIT0(); }
        __syncthreads();

        const uint32_t stage = sbase + (it & 1) * AT_STAGE;

        // ---- S = (Qh + Ql) @ K^T, fp16 ----
        float s[8][4];
#pragma unroll
        for (int j = 0; j < 8; j++)
#pragma unroll
            for (int r = 0; r < 4; r++) s[j][r] = 0.f;

#pragma unroll
        for (int ks = 0; ks < 4; ks++) {
            const int kof = ks * 16;
            uint32_t kf[8][2];
#pragma unroll
            for (int jp = 0; jp < 4; jp++) {
                int nrow = jp * 16 + ((lane >> 4) << 3) + (lane & 7);
                int bk   = kof + (((lane >> 3) & 1) << 3);
                uint32_t bd = stage + (uint32_t)(nrow * AT_STRIDE + bk) * 2;
                ldmatrix_x4(kf[jp*2][0], kf[jp*2][1], kf[jp*2+1][0], kf[jp*2+1][1], bd);
            }
#pragma unroll
            for (int j = 0; j < 8; j++) {
                mma_f16(s[j][0], s[j][1], s[j][2], s[j][3],
                        qfh[ks][0], qfh[ks][1], qfh[ks][2], qfh[ks][3],
                        kf[j][0], kf[j][1]);
                mma_f16(s[j][0], s[j][1], s[j][2], s[j][3],
                        qfl[ks][0], qfl[ks][1], qfl[ks][2], qfl[ks][3],
                        kf[j][0], kf[j][1]);
            }
        }

        // ---- online softmax ----
        float rm0 = -1e30f, rm1 = -1e30f;
#pragma unroll
        for (int j = 0; j < 8; j++) {
            rm0 = fmaxf(rm0, fmaxf(s[j][0], s[j][1]));
            rm1 = fmaxf(rm1, fmaxf(s[j][2], s[j][3]));
        }
        rm0 = fmaxf(rm0, __shfl_xor_sync(0xffffffffu, rm0, 1));
        rm0 = fmaxf(rm0, __shfl_xor_sync(0xffffffffu, rm0, 2));
        rm1 = fmaxf(rm1, __shfl_xor_sync(0xffffffffu, rm1, 1));
        rm1 = fmaxf(rm1, __shfl_xor_sync(0xffffffffu, rm1, 2));

        float nm0 = fmaxf(m0, rm0), nm1 = fmaxf(m1, rm1);
        float a0 = __expf(m0 - nm0), a1 = __expf(m1 - nm1);

        float rs0 = 0.f, rs1 = 0.f;
#pragma unroll
        for (int j = 0; j < 8; j++) {
            s[j][0] = __expf(s[j][0] - nm0);
            s[j][1] = __expf(s[j][1] - nm0);
            s[j][2] = __expf(s[j][2] - nm1);
            s[j][3] = __expf(s[j][3] - nm1);
            rs0 += s[j][0] + s[j][1];
            rs1 += s[j][2] + s[j][3];
        }
        rs0 += __shfl_xor_sync(0xffffffffu, rs0, 1);
        rs0 += __shfl_xor_sync(0xffffffffu, rs0, 2);
        rs1 += __shfl_xor_sync(0xffffffffu, rs1, 1);
        rs1 += __shfl_xor_sync(0xffffffffu, rs1, 2);

        l0 = l0 * a0 + rs0;  m0 = nm0;
        l1 = l1 * a1 + rs1;  m1 = nm1;

#pragma unroll
        for (int j = 0; j < 8; j++) {
            o[j][0] *= a0; o[j][1] *= a0;
            o[j][2] *= a1; o[j][3] *= a1;
        }

        // ---- O += P @ V (single fp16 P) ----
#pragma unroll
        for (int kk = 0; kk < 4; kk++) {
            uint32_t ph0 = pack_h2(s[2*kk][0],   s[2*kk][1]);
            uint32_t ph1 = pack_h2(s[2*kk][2],   s[2*kk][3]);
            uint32_t ph2 = pack_h2(s[2*kk+1][0], s[2*kk+1][1]);
            uint32_t ph3 = pack_h2(s[2*kk+1][2], s[2*kk+1][3]);
#pragma unroll
            for (int jp = 0; jp < 4; jp++) {
                int vrow = kk * 16 + (((lane >> 3) & 1) << 3) + (lane & 7);
                int vcol = jp * 16 + ((lane >> 4) << 3);
                uint32_t vd = stage + AT_TILE + (uint32_t)(vrow * AT_STRIDE + vcol) * 2;
                uint32_t v0, v1, v2, v3;
                ldmatrix_x4_trans(v0, v1, v2, v3, vd);
                mma_f16(o[jp*2][0],   o[jp*2][1],   o[jp*2][2],   o[jp*2][3],
                        ph0, ph1, ph2, ph3, v0, v1);
                mma_f16(o[jp*2+1][0], o[jp*2+1][1], o[jp*2+1][2], o[jp*2+1][3],
                        ph0, ph1, ph2, ph3, v2, v3);
            }
        }
        __syncthreads();
    }

    // ---- normalize + fp16 split-write for out-GEMM ----
    float inv0 = 1.f / l0, inv1 = 1.f / l1;
    const int orow = b * L_ + q0 + wid * 16 + (lane >> 2);
#pragma unroll
    for (int j = 0; j < 8; j++) {
        int col = basecol + j * 8 + (lane & 3) * 2;
        store_split2_h(ah, al, (size_t)orow * E_ + col,       o[j][0] * inv0, o[j][1] * inv0);
        store_split2_h(ah, al, (size_t)(orow + 8) * E_ + col, o[j][2] * inv1, o[j][3] * inv1);
    }
}

// ---------------------------------------------------------------------------
extern "C" void kernel_launch(void* const* d_in, const int* in_sizes, int n_in,
                              void* d_out, int out_size)
{
    const float* x    = (const float*)d_in[0];
    const float* Wqkv = (const float*)d_in[1];
    const float* bqkv = (const float*)d_in[2];
    const float* Wout = (const float*)d_in[3];
    const float* bout = (const float*)d_in[4];
    float* out = (float*)d_out;

    __half *xh, *xl, *wq16, *wo16, *q16h, *q16l, *k16, *v16, *ah, *al;
    cudaGetSymbolAddress((void**)&xh, g_xh);      cudaGetSymbolAddress((void**)&xl, g_xl);
    cudaGetSymbolAddress((void**)&wq16, g_wqkv16); cudaGetSymbolAddress((void**)&wo16, g_wo16);
    cudaGetSymbolAddress((void**)&q16h, g_q16h);  cudaGetSymbolAddress((void**)&q16l, g_q16l);
    cudaGetSymbolAddress((void**)&k16, g_k16);    cudaGetSymbolAddress((void**)&v16, g_v16);
    cudaGetSymbolAddress((void**)&ah, g_ah);      cudaGetSymbolAddress((void**)&al, g_al);

    static int attr_done = 0;
    if (!attr_done) {
        cudaFuncSetAttribute(gemm_split<0>,
                             cudaFuncAttributeMaxDynamicSharedMemorySize, GEMM_SMEM);
        cudaFuncSetAttribute(gemm_split<1>,
                             cudaFuncAttributeMaxDynamicSharedMemorySize, GEMM_SMEM);
        cudaFuncSetAttribute(attention_tc,
                             cudaFuncAttributeMaxDynamicSharedMemorySize, ATTN_SMEM);
        attr_done = 1;
    }

    // 0) prepass: x -> fp16 hi/lo, weights -> fp16
    conv_split_h<<<(M_ * E_ / 4 + 255) / 256, 256>>>(
        (const float4*)x, (__half2*)xh, (__half2*)xl, M_ * E_ / 4);
    conv_h<<<(3 * E_ * E_ / 4 + 255) / 256, 256>>>(
        (const float4*)Wqkv, (__half2*)wq16, 3 * E_ * E_ / 4);
    conv_h<<<(E_ * E_ / 4 + 255) / 256, 256>>>(
        (const float4*)Wout, (__half2*)wo16, E_ * E_ / 4);

    // 1) QKV projection -> fp16 attention operands
    gemm_split<1><<<dim3(3 * E_ / 128, M_ / 128), 256, GEMM_SMEM>>>(
        xh, xl, wq16, bqkv, nullptr,
        q16h, q16l, k16, v16, M_, 3 * E_, E_);

    // 2) attention -> fp16 split attn output
    attention_tc<<<dim3(L_ / 128, H_, B_), 256, ATTN_SMEM>>>(
        q16h, q16l, k16, v16, ah, al);

    // 3) out projection (fp32 epilogue)
    gemm_split<0><<<dim3(E_ / 128, M_ / 128), 256, GEMM_SMEM>>>(
        ah, al, wo16, bout, out,
        nullptr, nullptr, nullptr, nullptr, M_, E_, E_);
}

// round 10
// speedup vs baseline: 5.9758x; 1.2930x over previous
#include <cuda_runtime.h>
#include <cuda_bf16.h>
#include <cuda_fp16.h>
#include <math.h>
#include <stdint.h>

#define B_  2
#define L_  2048
#define E_  1024
#define H_  16
#define HD_ 64
#define M_  (B_ * L_)   // 4096

// ---------------------------------------------------------------------------
// Scratch (fp16 world)
// ---------------------------------------------------------------------------
__device__ __align__(16) __half g_x16[M_ * E_];       // x fp16
__device__ __align__(16) __half g_wqkv16[3 * E_ * E_];// Wqkv fp16
__device__ __align__(16) __half g_wo16[E_ * E_];      // Wout fp16
__device__ __align__(16) __half g_q16[M_ * E_];       // Q*0.125 fp16
__device__ __align__(16) __half g_k16[M_ * E_];       // K fp16
__device__ __align__(16) __half g_v16[M_ * E_];       // V fp16
__device__ __align__(16) __half g_ah[M_ * E_];        // attn out fp16 hi
__device__ __align__(16) __half g_al[M_ * E_];        // attn out fp16 residual

// ---------------------------------------------------------------------------
// helpers
// ---------------------------------------------------------------------------
__device__ __forceinline__ uint32_t smem_to_u32(const void* p) {
    uint32_t a;
    asm("{ .reg .u64 t; cvta.to.shared.u64 t, %1; cvt.u32.u64 %0, t; }" : "=r"(a) : "l"(p));
    return a;
}
__device__ __forceinline__ void cp_async16(uint32_t dst, const void* src) {
    asm volatile("cp.async.cg.shared.global [%0], [%1], 16;" :: "r"(dst), "l"(src));
}
#define CP_COMMIT() asm volatile("cp.async.commit_group;")
#define CP_WAIT1()  asm volatile("cp.async.wait_group 1;")
#define CP_WAIT0()  asm volatile("cp.async.wait_group 0;")

__device__ __forceinline__ void ldmatrix_x4(
    uint32_t& r0, uint32_t& r1, uint32_t& r2, uint32_t& r3, uint32_t addr)
{
    asm volatile("ldmatrix.sync.aligned.m8n8.x4.shared.b16 {%0,%1,%2,%3}, [%4];"
        : "=r"(r0), "=r"(r1), "=r"(r2), "=r"(r3) : "r"(addr));
}
__device__ __forceinline__ void ldmatrix_x4_trans(
    uint32_t& r0, uint32_t& r1, uint32_t& r2, uint32_t& r3, uint32_t addr)
{
    asm volatile("ldmatrix.sync.aligned.m8n8.x4.trans.shared.b16 {%0,%1,%2,%3}, [%4];"
        : "=r"(r0), "=r"(r1), "=r"(r2), "=r"(r3) : "r"(addr));
}
__device__ __forceinline__ void mma_f16(
    float& c0, float& c1, float& c2, float& c3,
    uint32_t a0, uint32_t a1, uint32_t a2, uint32_t a3, uint32_t b0, uint32_t b1)
{
    asm volatile(
        "mma.sync.aligned.m16n8k16.row.col.f32.f16.f16.f32 "
        "{%0,%1,%2,%3}, {%4,%5,%6,%7}, {%8,%9}, {%0,%1,%2,%3};"
        : "+f"(c0), "+f"(c1), "+f"(c2), "+f"(c3)
        : "r"(a0), "r"(a1), "r"(a2), "r"(a3), "r"(b0), "r"(b1));
}
__device__ __forceinline__ uint32_t pack_h2(float a, float b) {
    __half2 p = __floats2half2_rn(a, b);
    return *(uint32_t*)&p;
}
__device__ __forceinline__ void store_split2_h(
    __half* hi, __half* lo, size_t idx, float a, float b)
{
    __half ha = __float2half_rn(a);
    __half hb = __float2half_rn(b);
    *(__half2*)(hi + idx) = __half2(ha, hb);
    *(__half2*)(lo + idx) = __floats2half2_rn(a - __half2float(ha),
                                              b - __half2float(hb));
}

// ---------------------------------------------------------------------------
// Prepass: fp32 -> fp16
// ---------------------------------------------------------------------------
__global__ void conv_h(const float4* __restrict__ src,
                       __half2* __restrict__ dst, int n4)
{
    int i = blockIdx.x * blockDim.x + threadIdx.x;
    if (i >= n4) return;
    float4 t = src[i];
    dst[2*i]   = __floats2half2_rn(t.x, t.y);
    dst[2*i+1] = __floats2half2_rn(t.z, t.w);
}

// ---------------------------------------------------------------------------
// GEMM: C = (Ah [+ Al]) @ Wh^T (+bias), ASPLIT fp16 MMAs per atom.
// BM=128, BN=128, BK=32; 256 threads, 8 warps. cp.async double-buffered.
// EPI=0: fp32+bias -> Cf. EPI=1: qkv epilogue -> fp16 attention operands.
// ---------------------------------------------------------------------------
#define GT_STRIDE 40
#define GT_TILE   (128 * GT_STRIDE * 2)   // 10240 B

template<int EPI, int ASPLIT>
__global__ __launch_bounds__(256, 2) void gemm_split(
    const __half* __restrict__ Ahi, const __half* __restrict__ Alo,
    const __half* __restrict__ Wh,
    const float* __restrict__ bias, float* __restrict__ Cf,
    __half* __restrict__ q16, __half* __restrict__ k16, __half* __restrict__ v16,
    int M, int N, int K)
{
    constexpr int NT = ASPLIT + 1;            // tiles per stage
    constexpr int STAGE = NT * GT_TILE;
    extern __shared__ char smg[];
    const uint32_t sbase = smem_to_u32(smg);

    const int bm   = blockIdx.y * 128;
    const int bn   = blockIdx.x * 128;
    const int tid  = threadIdx.x;
    const int wid  = tid >> 5;
    const int lane = tid & 31;
    const int wm   = wid >> 2;
    const int wn   = wid & 3;

    float c[4][4][4];
#pragma unroll
    for (int i = 0; i < 4; i++)
#pragma unroll
        for (int j = 0; j < 4; j++)
#pragma unroll
            for (int r = 0; r < 4; r++) c[i][j][r] = 0.f;

    auto load_stage = [&](int s, int k0) {
        const uint32_t base = sbase + s * STAGE;
        const __half* srcs[3];
        srcs[0] = Ahi + (size_t)bm * K + k0;
        srcs[1] = (ASPLIT == 2) ? Alo + (size_t)bm * K + k0
                                : Wh  + (size_t)bn * K + k0;
        srcs[2] = Wh + (size_t)bn * K + k0;   // used only when ASPLIT==2
#pragma unroll
        for (int t = 0; t < NT; t++) {
#pragma unroll
            for (int i = 0; i < 2; i++) {
                int chunk = tid * 2 + i;        // 0..511
                int row   = chunk >> 2;
                int cc    = chunk & 3;
                cp_async16(base + t * GT_TILE + row * (GT_STRIDE * 2) + cc * 16,
                           srcs[t] + (size_t)row * K + cc * 8);
            }
        }
    };

    load_stage(0, 0);
    CP_COMMIT();

    const int niter = K / 32;
    for (int it = 0; it < niter; it++) {
        if (it + 1 < niter) { load_stage((it + 1) & 1, (it + 1) * 32); CP_COMMIT(); CP_WAIT1(); }
        else                { CP_WAIT0(); }
        __syncthreads();

        const uint32_t stage = sbase + (it & 1) * STAGE;
        const uint32_t wtile = stage + (NT - 1) * GT_TILE;
#pragma unroll
        for (int ks = 0; ks < 2; ks++) {
            const int kof = ks * 16;
            uint32_t ahi[4][4], alo[4][4], bfr[4][2];
#pragma unroll
            for (int i = 0; i < 4; i++) {
                int m0 = wm * 64 + i * 16;
                uint32_t ad = stage +
                    (uint32_t)((m0 + (lane & 15)) * GT_STRIDE + kof + (lane >> 4) * 8) * 2;
                ldmatrix_x4(ahi[i][0], ahi[i][1], ahi[i][2], ahi[i][3], ad);
                if (ASPLIT == 2)
                    ldmatrix_x4(alo[i][0], alo[i][1], alo[i][2], alo[i][3], ad + GT_TILE);
            }
#pragma unroll
            for (int jp = 0; jp < 2; jp++) {
                int n0 = wn * 32 + jp * 16;
                int nrow = n0 + ((lane >> 4) << 3) + (lane & 7);
                int bk   = kof + (((lane >> 3) & 1) << 3);
                uint32_t bd = wtile + (uint32_t)(nrow * GT_STRIDE + bk) * 2;
                ldmatrix_x4(bfr[jp*2][0], bfr[jp*2][1], bfr[jp*2+1][0], bfr[jp*2+1][1], bd);
            }
#pragma unroll
            for (int i = 0; i < 4; i++)
#pragma unroll
                for (int j = 0; j < 4; j++) {
                    mma_f16(c[i][j][0], c[i][j][1], c[i][j][2], c[i][j][3],
                            ahi[i][0], ahi[i][1], ahi[i][2], ahi[i][3],
                            bfr[j][0], bfr[j][1]);
                    if (ASPLIT == 2)
                        mma_f16(c[i][j][0], c[i][j][1], c[i][j][2], c[i][j][3],
                                alo[i][0], alo[i][1], alo[i][2], alo[i][3],
                                bfr[j][0], bfr[j][1]);
                }
        }
        __syncthreads();
    }

    // ---- epilogue ----
    const int g4 = lane >> 2;
    const int t4 = lane & 3;
    if (EPI == 0) {
#pragma unroll
        for (int i = 0; i < 4; i++) {
            int row0 = bm + wm * 64 + i * 16 + g4;
#pragma unroll
            for (int j = 0; j < 4; j++) {
                int col = bn + wn * 32 + j * 8 + t4 * 2;
                float bx = bias[col], by = bias[col + 1];
                *(float2*)(Cf + (size_t)row0 * N + col) =
                    make_float2(c[i][j][0] + bx, c[i][j][1] + by);
                *(float2*)(Cf + (size_t)(row0 + 8) * N + col) =
                    make_float2(c[i][j][2] + bx, c[i][j][3] + by);
            }
        }
    } else {
        const int seg     = bn >> 10;          // 0=Q, 1=K, 2=V
        const int segbase = bn & 1023;
#pragma unroll
        for (int i = 0; i < 4; i++) {
            int row0 = bm + wm * 64 + i * 16 + g4;
#pragma unroll
            for (int j = 0; j < 4; j++) {
                int colg = bn + wn * 32 + j * 8 + t4 * 2;
                int cols = segbase + wn * 32 + j * 8 + t4 * 2;
                float bx = bias[colg], by = bias[colg + 1];
                float v0 = c[i][j][0] + bx, v1 = c[i][j][1] + by;
                float v2 = c[i][j][2] + bx, v3 = c[i][j][3] + by;
                size_t i0 = (size_t)row0 * E_ + cols;
                size_t i1 = (size_t)(row0 + 8) * E_ + cols;
                if (seg == 0) {
                    *(__half2*)(q16 + i0) = __floats2half2_rn(v0 * 0.125f, v1 * 0.125f);
                    *(__half2*)(q16 + i1) = __floats2half2_rn(v2 * 0.125f, v3 * 0.125f);
                } else if (seg == 1) {
                    *(__half2*)(k16 + i0) = __floats2half2_rn(v0, v1);
                    *(__half2*)(k16 + i1) = __floats2half2_rn(v2, v3);
                } else {
                    *(__half2*)(v16 + i0) = __floats2half2_rn(v0, v1);
                    *(__half2*)(v16 + i1) = __floats2half2_rn(v2, v3);
                }
            }
        }
    }
}

#define GEMM_SMEM_QKV (2 * 2 * GT_TILE)   // 40960
#define GEMM_SMEM_OUT (2 * 3 * GT_TILE)   // 61440

// ---------------------------------------------------------------------------
// Flash attention: S = Q16 @ K16^T (1 mma); O += P16 @ V16 (1 mma).
// Block: (b, h, 128 q-rows). K-tiles of 64. cp.async double buffer.
// ---------------------------------------------------------------------------
#define AT_STRIDE 72
#define AT_TILE   (64 * AT_STRIDE * 2)     // 9216
#define AT_STAGE  (2 * AT_TILE)            // 18432 (K16, V16)
#define ATTN_SMEM (2 * AT_STAGE)           // 36864

__global__ __launch_bounds__(256) void attention_tc(
    const __half* __restrict__ q16,
    const __half* __restrict__ k16, const __half* __restrict__ v16,
    __half* __restrict__ ah, __half* __restrict__ al)
{
    extern __shared__ char sma[];
    const uint32_t sbase = smem_to_u32(sma);

    const int q0   = blockIdx.x * 128;
    const int h    = blockIdx.y;
    const int b    = blockIdx.z;
    const int tid  = threadIdx.x;
    const int wid  = tid >> 5;
    const int lane = tid & 31;
    const int basecol = h * HD_;

    // ---- Q fragments directly from global (ldmatrix A-frag layout) ----
    uint32_t qf[4][4];
    {
        const int r0 = b * L_ + q0 + wid * 16 + (lane >> 2);
        const int c0 = basecol + (lane & 3) * 2;
#pragma unroll
        for (int ks = 0; ks < 4; ks++) {
            size_t i00 = (size_t)r0 * E_ + c0 + ks * 16;
            qf[ks][0] = *(const uint32_t*)(q16 + i00);
            qf[ks][1] = *(const uint32_t*)(q16 + i00 + 8 * E_);
            qf[ks][2] = *(const uint32_t*)(q16 + i00 + 8);
            qf[ks][3] = *(const uint32_t*)(q16 + i00 + 8 * E_ + 8);
        }
    }

    auto load_kv = [&](int s, int kt) {
        const uint32_t base = sbase + s * AT_STAGE;
        const int rowg = b * L_ + kt;
#pragma unroll
        for (int i = 0; i < 2; i++) {
            int chunk = tid * 2 + i;        // 0..511
            int row   = chunk >> 3;
            int cc    = chunk & 7;
            size_t src = (size_t)(rowg + row) * E_ + basecol + cc * 8;
            uint32_t doff = row * (AT_STRIDE * 2) + cc * 16;
            cp_async16(base + doff,           k16 + src);
            cp_async16(base + AT_TILE + doff, v16 + src);
        }
    };

    load_kv(0, 0);
    CP_COMMIT();

    float o[8][4];
#pragma unroll
    for (int j = 0; j < 8; j++)
#pragma unroll
        for (int r = 0; r < 4; r++) o[j][r] = 0.f;
    float m0 = -1e30f, m1 = -1e30f, l0 = 0.f, l1 = 0.f;

    const int NTILE = L_ / 64;
    for (int it = 0; it < NTILE; it++) {
        if (it + 1 < NTILE) { load_kv((it + 1) & 1, (it + 1) * 64); CP_COMMIT(); CP_WAIT1(); }
        else                { CP_WAIT0(); }
        __syncthreads();

        const uint32_t stage = sbase + (it & 1) * AT_STAGE;

        // ---- S = Q @ K^T, fp16 ----
        float s[8][4];
#pragma unroll
        for (int j = 0; j < 8; j++)
#pragma unroll
            for (int r = 0; r < 4; r++) s[j][r] = 0.f;

#pragma unroll
        for (int ks = 0; ks < 4; ks++) {
            const int kof = ks * 16;
            uint32_t kf[8][2];
#pragma unroll
            for (int jp = 0; jp < 4; jp++) {
                int nrow = jp * 16 + ((lane >> 4) << 3) + (lane & 7);
                int bk   = kof + (((lane >> 3) & 1) << 3);
                uint32_t bd = stage + (uint32_t)(nrow * AT_STRIDE + bk) * 2;
                ldmatrix_x4(kf[jp*2][0], kf[jp*2][1], kf[jp*2+1][0], kf[jp*2+1][1], bd);
            }
#pragma unroll
            for (int j = 0; j < 8; j++)
                mma_f16(s[j][0], s[j][1], s[j][2], s[j][3],
                        qf[ks][0], qf[ks][1], qf[ks][2], qf[ks][3],
                        kf[j][0], kf[j][1]);
        }

        // ---- online softmax ----
        float rm0 = -1e30f, rm1 = -1e30f;
#pragma unroll
        for (int j = 0; j < 8; j++) {
            rm0 = fmaxf(rm0, fmaxf(s[j][0], s[j][1]));
            rm1 = fmaxf(rm1, fmaxf(s[j][2], s[j][3]));
        }
        rm0 = fmaxf(rm0, __shfl_xor_sync(0xffffffffu, rm0, 1));
        rm0 = fmaxf(rm0, __shfl_xor_sync(0xffffffffu, rm0, 2));
        rm1 = fmaxf(rm1, __shfl_xor_sync(0xffffffffu, rm1, 1));
        rm1 = fmaxf(rm1, __shfl_xor_sync(0xffffffffu, rm1, 2));

        float nm0 = fmaxf(m0, rm0), nm1 = fmaxf(m1, rm1);
        float a0 = __expf(m0 - nm0), a1 = __expf(m1 - nm1);

        float rs0 = 0.f, rs1 = 0.f;
#pragma unroll
        for (int j = 0; j < 8; j++) {
            s[j][0] = __expf(s[j][0] - nm0);
            s[j][1] = __expf(s[j][1] - nm0);
            s[j][2] = __expf(s[j][2] - nm1);
            s[j][3] = __expf(s[j][3] - nm1);
            rs0 += s[j][0] + s[j][1];
            rs1 += s[j][2] + s[j][3];
        }
        rs0 += __shfl_xor_sync(0xffffffffu, rs0, 1);
        rs0 += __shfl_xor_sync(0xffffffffu, rs0, 2);
        rs1 += __shfl_xor_sync(0xffffffffu, rs1, 1);
        rs1 += __shfl_xor_sync(0xffffffffu, rs1, 2);

        l0 = l0 * a0 + rs0;  m0 = nm0;
        l1 = l1 * a1 + rs1;  m1 = nm1;

#pragma unroll
        for (int j = 0; j < 8; j++) {
            o[j][0] *= a0; o[j][1] *= a0;
            o[j][2] *= a1; o[j][3] *= a1;
        }

        // ---- O += P @ V (single fp16 P) ----
#pragma unroll
        for (int kk = 0; kk < 4; kk++) {
            uint32_t ph0 = pack_h2(s[2*kk][0],   s[2*kk][1]);
            uint32_t ph1 = pack_h2(s[2*kk][2],   s[2*kk][3]);
            uint32_t ph2 = pack_h2(s[2*kk+1][0], s[2*kk+1][1]);
            uint32_t ph3 = pack_h2(s[2*kk+1][2], s[2*kk+1][3]);
#pragma unroll
            for (int jp = 0; jp < 4; jp++) {
                int vrow = kk * 16 + (((lane >> 3) & 1) << 3) + (lane & 7);
                int vcol = jp * 16 + ((lane >> 4) << 3);
                uint32_t vd = stage + AT_TILE + (uint32_t)(vrow * AT_STRIDE + vcol) * 2;
                uint32_t v0, v1, v2, v3;
                ldmatrix_x4_trans(v0, v1, v2, v3, vd);
                mma_f16(o[jp*2][0],   o[jp*2][1],   o[jp*2][2],   o[jp*2][3],
                        ph0, ph1, ph2, ph3, v0, v1);
                mma_f16(o[jp*2+1][0], o[jp*2+1][1], o[jp*2+1][2], o[jp*2+1][3],
                        ph0, ph1, ph2, ph3, v2, v3);
            }
        }
        __syncthreads();
    }

    // ---- normalize + fp16 split-write for out-GEMM ----
    float inv0 = 1.f / l0, inv1 = 1.f / l1;
    const int orow = b * L_ + q0 + wid * 16 + (lane >> 2);
#pragma unroll
    for (int j = 0; j < 8; j++) {
        int col = basecol + j * 8 + (lane & 3) * 2;
        store_split2_h(ah, al, (size_t)orow * E_ + col,       o[j][0] * inv0, o[j][1] * inv0);
        store_split2_h(ah, al, (size_t)(orow + 8) * E_ + col, o[j][2] * inv1, o[j][3] * inv1);
    }
}

// ---------------------------------------------------------------------------
extern "C" void kernel_launch(void* const* d_in, const int* in_sizes, int n_in,
                              void* d_out, int out_size)
{
    const float* x    = (const float*)d_in[0];
    const float* Wqkv = (const float*)d_in[1];
    const float* bqkv = (const float*)d_in[2];
    const float* Wout = (const float*)d_in[3];
    const float* bout = (const float*)d_in[4];
    float* out = (float*)d_out;

    __half *x16, *wq16, *wo16, *q16, *k16, *v16, *ah, *al;
    cudaGetSymbolAddress((void**)&x16, g_x16);
    cudaGetSymbolAddress((void**)&wq16, g_wqkv16);
    cudaGetSymbolAddress((void**)&wo16, g_wo16);
    cudaGetSymbolAddress((void**)&q16, g_q16);
    cudaGetSymbolAddress((void**)&k16, g_k16);
    cudaGetSymbolAddress((void**)&v16, g_v16);
    cudaGetSymbolAddress((void**)&ah, g_ah);
    cudaGetSymbolAddress((void**)&al, g_al);

    static int attr_done = 0;
    if (!attr_done) {
        cudaFuncSetAttribute((const void*)gemm_split<1, 1>,
                             cudaFuncAttributeMaxDynamicSharedMemorySize, GEMM_SMEM_QKV);
        cudaFuncSetAttribute((const void*)gemm_split<0, 2>,
                             cudaFuncAttributeMaxDynamicSharedMemorySize, GEMM_SMEM_OUT);
        cudaFuncSetAttribute(attention_tc,
                             cudaFuncAttributeMaxDynamicSharedMemorySize, ATTN_SMEM);
        attr_done = 1;
    }

    // 0) prepass: fp32 -> fp16
    conv_h<<<(M_ * E_ / 4 + 255) / 256, 256>>>(
        (const float4*)x, (__half2*)x16, M_ * E_ / 4);
    conv_h<<<(3 * E_ * E_ / 4 + 255) / 256, 256>>>(
        (const float4*)Wqkv, (__half2*)wq16, 3 * E_ * E_ / 4);
    conv_h<<<(E_ * E_ / 4 + 255) / 256, 256>>>(
        (const float4*)Wout, (__half2*)wo16, E_ * E_ / 4);

    // 1) QKV projection (1 fp16 MMA/atom) -> fp16 attention operands
    gemm_split<1, 1><<<dim3(3 * E_ / 128, M_ / 128), 256, GEMM_SMEM_QKV>>>(
        x16, nullptr, wq16, bqkv, nullptr,
        q16, k16, v16, M_, 3 * E_, E_);

    // 2) attention (1 QK mma + 1 PV mma) -> fp16 split attn output
    attention_tc<<<dim3(L_ / 128, H_, B_), 256, ATTN_SMEM>>>(
        q16, k16, v16, ah, al);

    // 3) out projection (ah+al split, 2 MMA; fp32 epilogue)
    gemm_split<0, 2><<<dim3(E_ / 128, M_ / 128), 256, GEMM_SMEM_OUT>>>(
        ah, al, wo16, bout, out,
        nullptr, nullptr, nullptr, M_, E_, E_);
}

// round 11
// speedup vs baseline: 6.2891x; 1.0524x over previous
#include <cuda_runtime.h>
#include <cuda_bf16.h>
#include <cuda_fp16.h>
#include <math.h>
#include <stdint.h>

#define B_  2
#define L_  2048
#define E_  1024
#define H_  16
#define HD_ 64
#define M_  (B_ * L_)   // 4096

// ---------------------------------------------------------------------------
// Scratch (fp16 world)
// ---------------------------------------------------------------------------
__device__ __align__(16) __half g_x16[M_ * E_];       // x fp16
__device__ __align__(16) __half g_wqkv16[3 * E_ * E_];// Wqkv fp16
__device__ __align__(16) __half g_wo16[E_ * E_];      // Wout fp16
__device__ __align__(16) __half g_q16[M_ * E_];       // Q*0.125 fp16
__device__ __align__(16) __half g_k16[M_ * E_];       // K fp16
__device__ __align__(16) __half g_v16[M_ * E_];       // V fp16
__device__ __align__(16) __half g_a16[M_ * E_];       // attn out fp16

// ---------------------------------------------------------------------------
// helpers
// ---------------------------------------------------------------------------
__device__ __forceinline__ uint32_t smem_to_u32(const void* p) {
    uint32_t a;
    asm("{ .reg .u64 t; cvta.to.shared.u64 t, %1; cvt.u32.u64 %0, t; }" : "=r"(a) : "l"(p));
    return a;
}
__device__ __forceinline__ void cp_async16(uint32_t dst, const void* src) {
    asm volatile("cp.async.cg.shared.global [%0], [%1], 16;" :: "r"(dst), "l"(src));
}
#define CP_COMMIT() asm volatile("cp.async.commit_group;")
#define CP_WAIT1()  asm volatile("cp.async.wait_group 1;")
#define CP_WAIT0()  asm volatile("cp.async.wait_group 0;")

__device__ __forceinline__ void ldmatrix_x4(
    uint32_t& r0, uint32_t& r1, uint32_t& r2, uint32_t& r3, uint32_t addr)
{
    asm volatile("ldmatrix.sync.aligned.m8n8.x4.shared.b16 {%0,%1,%2,%3}, [%4];"
        : "=r"(r0), "=r"(r1), "=r"(r2), "=r"(r3) : "r"(addr));
}
__device__ __forceinline__ void ldmatrix_x4_trans(
    uint32_t& r0, uint32_t& r1, uint32_t& r2, uint32_t& r3, uint32_t addr)
{
    asm volatile("ldmatrix.sync.aligned.m8n8.x4.trans.shared.b16 {%0,%1,%2,%3}, [%4];"
        : "=r"(r0), "=r"(r1), "=r"(r2), "=r"(r3) : "r"(addr));
}
__device__ __forceinline__ void mma_f16(
    float& c0, float& c1, float& c2, float& c3,
    uint32_t a0, uint32_t a1, uint32_t a2, uint32_t a3, uint32_t b0, uint32_t b1)
{
    asm volatile(
        "mma.sync.aligned.m16n8k16.row.col.f32.f16.f16.f32 "
        "{%0,%1,%2,%3}, {%4,%5,%6,%7}, {%8,%9}, {%0,%1,%2,%3};"
        : "+f"(c0), "+f"(c1), "+f"(c2), "+f"(c3)
        : "r"(a0), "r"(a1), "r"(a2), "r"(a3), "r"(b0), "r"(b1));
}
__device__ __forceinline__ uint32_t pack_h2(float a, float b) {
    __half2 p = __floats2half2_rn(a, b);
    return *(uint32_t*)&p;
}

// ---------------------------------------------------------------------------
// Prepass: fp32 -> fp16
// ---------------------------------------------------------------------------
__global__ void conv_h(const float4* __restrict__ src,
                       __half2* __restrict__ dst, int n4)
{
    int i = blockIdx.x * blockDim.x + threadIdx.x;
    if (i >= n4) return;
    float4 t = src[i];
    dst[2*i]   = __floats2half2_rn(t.x, t.y);
    dst[2*i+1] = __floats2half2_rn(t.z, t.w);
}

// ---------------------------------------------------------------------------
// GEMM: C = A16 @ W16^T (+bias), single fp16 MMA per atom.
// BM=128, BN=128, BK=64; 256 threads, 8 warps (warp tile 64x32).
// cp.async double-buffered, stride-72 rows (conflict-free ldmatrix).
// EPI=0: fp32+bias -> Cf. EPI=1: qkv epilogue -> fp16 attention operands.
// ---------------------------------------------------------------------------
#define GT_STRIDE 72
#define GT_TILE   (128 * GT_STRIDE * 2)   // 18432 B
#define GT_STAGE  (2 * GT_TILE)           // 36864 B (A, W)
#define GEMM_SMEM (2 * GT_STAGE)          // 73728 B

template<int EPI>
__global__ __launch_bounds__(256, 2) void gemm_tc(
    const __half* __restrict__ A16, const __half* __restrict__ W16,
    const float* __restrict__ bias, float* __restrict__ Cf,
    __half* __restrict__ q16, __half* __restrict__ k16, __half* __restrict__ v16,
    int M, int N, int K)
{
    extern __shared__ char smg[];
    const uint32_t sbase = smem_to_u32(smg);

    const int bm   = blockIdx.y * 128;
    const int bn   = blockIdx.x * 128;
    const int tid  = threadIdx.x;
    const int wid  = tid >> 5;
    const int lane = tid & 31;
    const int wm   = wid >> 2;
    const int wn   = wid & 3;

    float c[4][4][4];
#pragma unroll
    for (int i = 0; i < 4; i++)
#pragma unroll
        for (int j = 0; j < 4; j++)
#pragma unroll
            for (int r = 0; r < 4; r++) c[i][j][r] = 0.f;

    auto load_stage = [&](int s, int k0) {
        const uint32_t base = sbase + s * GT_STAGE;
        const __half* srcA = A16 + (size_t)bm * K + k0;
        const __half* srcW = W16 + (size_t)bn * K + k0;
        // per tile: 128 rows x 8 chunks(16B) = 1024 chunks; 4 per thread
#pragma unroll
        for (int i = 0; i < 4; i++) {
            int chunk = tid * 4 + i;
            int row   = chunk >> 3;
            int cc    = chunk & 7;
            uint32_t doff = row * (GT_STRIDE * 2) + cc * 16;
            cp_async16(base + doff,           srcA + (size_t)row * K + cc * 8);
            cp_async16(base + GT_TILE + doff, srcW + (size_t)row * K + cc * 8);
        }
    };

    load_stage(0, 0);
    CP_COMMIT();

    const int niter = K / 64;
    for (int it = 0; it < niter; it++) {
        if (it + 1 < niter) { load_stage((it + 1) & 1, (it + 1) * 64); CP_COMMIT(); CP_WAIT1(); }
        else                { CP_WAIT0(); }
        __syncthreads();

        const uint32_t stage = sbase + (it & 1) * GT_STAGE;
#pragma unroll
        for (int ks = 0; ks < 4; ks++) {
            const int kof = ks * 16;
            uint32_t af[4][4], bfr[4][2];
#pragma unroll
            for (int i = 0; i < 4; i++) {
                int m0 = wm * 64 + i * 16;
                uint32_t ad = stage +
                    (uint32_t)((m0 + (lane & 15)) * GT_STRIDE + kof + (lane >> 4) * 8) * 2;
                ldmatrix_x4(af[i][0], af[i][1], af[i][2], af[i][3], ad);
            }
#pragma unroll
            for (int jp = 0; jp < 2; jp++) {
                int n0 = wn * 32 + jp * 16;
                int nrow = n0 + ((lane >> 4) << 3) + (lane & 7);
                int bk   = kof + (((lane >> 3) & 1) << 3);
                uint32_t bd = stage + GT_TILE + (uint32_t)(nrow * GT_STRIDE + bk) * 2;
                ldmatrix_x4(bfr[jp*2][0], bfr[jp*2][1], bfr[jp*2+1][0], bfr[jp*2+1][1], bd);
            }
#pragma unroll
            for (int i = 0; i < 4; i++)
#pragma unroll
                for (int j = 0; j < 4; j++)
                    mma_f16(c[i][j][0], c[i][j][1], c[i][j][2], c[i][j][3],
                            af[i][0], af[i][1], af[i][2], af[i][3],
                            bfr[j][0], bfr[j][1]);
        }
        __syncthreads();
    }

    // ---- epilogue ----
    const int g4 = lane >> 2;
    const int t4 = lane & 3;
    if (EPI == 0) {
#pragma unroll
        for (int i = 0; i < 4; i++) {
            int row0 = bm + wm * 64 + i * 16 + g4;
#pragma unroll
            for (int j = 0; j < 4; j++) {
                int col = bn + wn * 32 + j * 8 + t4 * 2;
                float bx = bias[col], by = bias[col + 1];
                *(float2*)(Cf + (size_t)row0 * N + col) =
                    make_float2(c[i][j][0] + bx, c[i][j][1] + by);
                *(float2*)(Cf + (size_t)(row0 + 8) * N + col) =
                    make_float2(c[i][j][2] + bx, c[i][j][3] + by);
            }
        }
    } else {
        const int seg     = bn >> 10;          // 0=Q, 1=K, 2=V
        const int segbase = bn & 1023;
#pragma unroll
        for (int i = 0; i < 4; i++) {
            int row0 = bm + wm * 64 + i * 16 + g4;
#pragma unroll
            for (int j = 0; j < 4; j++) {
                int colg = bn + wn * 32 + j * 8 + t4 * 2;
                int cols = segbase + wn * 32 + j * 8 + t4 * 2;
                float bx = bias[colg], by = bias[colg + 1];
                float v0 = c[i][j][0] + bx, v1 = c[i][j][1] + by;
                float v2 = c[i][j][2] + bx, v3 = c[i][j][3] + by;
                size_t i0 = (size_t)row0 * E_ + cols;
                size_t i1 = (size_t)(row0 + 8) * E_ + cols;
                if (seg == 0) {
                    *(__half2*)(q16 + i0) = __floats2half2_rn(v0 * 0.125f, v1 * 0.125f);
                    *(__half2*)(q16 + i1) = __floats2half2_rn(v2 * 0.125f, v3 * 0.125f);
                } else if (seg == 1) {
                    *(__half2*)(k16 + i0) = __floats2half2_rn(v0, v1);
                    *(__half2*)(k16 + i1) = __floats2half2_rn(v2, v3);
                } else {
                    *(__half2*)(v16 + i0) = __floats2half2_rn(v0, v1);
                    *(__half2*)(v16 + i1) = __floats2half2_rn(v2, v3);
                }
            }
        }
    }
}

// ---------------------------------------------------------------------------
// Flash attention: S = Q16 @ K16^T (1 mma); O += P16 @ V16 (1 mma).
// Block: (b, h, 128 q-rows). K-tiles of 64. cp.async double buffer.
// Output: single fp16 array (feeds out-GEMM).
// ---------------------------------------------------------------------------
#define AT_STRIDE 72
#define AT_TILE   (64 * AT_STRIDE * 2)     // 9216
#define AT_STAGE  (2 * AT_TILE)            // 18432 (K16, V16)
#define ATTN_SMEM (2 * AT_STAGE)           // 36864

__global__ __launch_bounds__(256) void attention_tc(
    const __half* __restrict__ q16,
    const __half* __restrict__ k16, const __half* __restrict__ v16,
    __half* __restrict__ a16)
{
    extern __shared__ char sma[];
    const uint32_t sbase = smem_to_u32(sma);

    const int q0   = blockIdx.x * 128;
    const int h    = blockIdx.y;
    const int b    = blockIdx.z;
    const int tid  = threadIdx.x;
    const int wid  = tid >> 5;
    const int lane = tid & 31;
    const int basecol = h * HD_;

    // ---- Q fragments directly from global (ldmatrix A-frag layout) ----
    uint32_t qf[4][4];
    {
        const int r0 = b * L_ + q0 + wid * 16 + (lane >> 2);
        const int c0 = basecol + (lane & 3) * 2;
#pragma unroll
        for (int ks = 0; ks < 4; ks++) {
            size_t i00 = (size_t)r0 * E_ + c0 + ks * 16;
            qf[ks][0] = *(const uint32_t*)(q16 + i00);
            qf[ks][1] = *(const uint32_t*)(q16 + i00 + 8 * E_);
            qf[ks][2] = *(const uint32_t*)(q16 + i00 + 8);
            qf[ks][3] = *(const uint32_t*)(q16 + i00 + 8 * E_ + 8);
        }
    }

    auto load_kv = [&](int s, int kt) {
        const uint32_t base = sbase + s * AT_STAGE;
        const int rowg = b * L_ + kt;
#pragma unroll
        for (int i = 0; i < 2; i++) {
            int chunk = tid * 2 + i;        // 0..511
            int row   = chunk >> 3;
            int cc    = chunk & 7;
            size_t src = (size_t)(rowg + row) * E_ + basecol + cc * 8;
            uint32_t doff = row * (AT_STRIDE * 2) + cc * 16;
            cp_async16(base + doff,           k16 + src);
            cp_async16(base + AT_TILE + doff, v16 + src);
        }
    };

    load_kv(0, 0);
    CP_COMMIT();

    float o[8][4];
#pragma unroll
    for (int j = 0; j < 8; j++)
#pragma unroll
        for (int r = 0; r < 4; r++) o[j][r] = 0.f;
    float m0 = -1e30f, m1 = -1e30f, l0 = 0.f, l1 = 0.f;

    const int NTILE = L_ / 64;
    for (int it = 0; it < NTILE; it++) {
        if (it + 1 < NTILE) { load_kv((it + 1) & 1, (it + 1) * 64); CP_COMMIT(); CP_WAIT1(); }
        else                { CP_WAIT0(); }
        __syncthreads();

        const uint32_t stage = sbase + (it & 1) * AT_STAGE;

        // ---- S = Q @ K^T, fp16 ----
        float s[8][4];
#pragma unroll
        for (int j = 0; j < 8; j++)
#pragma unroll
            for (int r = 0; r < 4; r++) s[j][r] = 0.f;

#pragma unroll
        for (int ks = 0; ks < 4; ks++) {
            const int kof = ks * 16;
            uint32_t kf[8][2];
#pragma unroll
            for (int jp = 0; jp < 4; jp++) {
                int nrow = jp * 16 + ((lane >> 4) << 3) + (lane & 7);
                int bk   = kof + (((lane >> 3) & 1) << 3);
                uint32_t bd = stage + (uint32_t)(nrow * AT_STRIDE + bk) * 2;
                ldmatrix_x4(kf[jp*2][0], kf[jp*2][1], kf[jp*2+1][0], kf[jp*2+1][1], bd);
            }
#pragma unroll
            for (int j = 0; j < 8; j++)
                mma_f16(s[j][0], s[j][1], s[j][2], s[j][3],
                        qf[ks][0], qf[ks][1], qf[ks][2], qf[ks][3],
                        kf[j][0], kf[j][1]);
        }

        // ---- online softmax ----
        float rm0 = -1e30f, rm1 = -1e30f;
#pragma unroll
        for (int j = 0; j < 8; j++) {
            rm0 = fmaxf(rm0, fmaxf(s[j][0], s[j][1]));
            rm1 = fmaxf(rm1, fmaxf(s[j][2], s[j][3]));
        }
        rm0 = fmaxf(rm0, __shfl_xor_sync(0xffffffffu, rm0, 1));
        rm0 = fmaxf(rm0, __shfl_xor_sync(0xffffffffu, rm0, 2));
        rm1 = fmaxf(rm1, __shfl_xor_sync(0xffffffffu, rm1, 1));
        rm1 = fmaxf(rm1, __shfl_xor_sync(0xffffffffu, rm1, 2));

        float nm0 = fmaxf(m0, rm0), nm1 = fmaxf(m1, rm1);
        float a0 = __expf(m0 - nm0), a1 = __expf(m1 - nm1);

        float rs0 = 0.f, rs1 = 0.f;
#pragma unroll
        for (int j = 0; j < 8; j++) {
            s[j][0] = __expf(s[j][0] - nm0);
            s[j][1] = __expf(s[j][1] - nm0);
            s[j][2] = __expf(s[j][2] - nm1);
            s[j][3] = __expf(s[j][3] - nm1);
            rs0 += s[j][0] + s[j][1];
            rs1 += s[j][2] + s[j][3];
        }
        rs0 += __shfl_xor_sync(0xffffffffu, rs0, 1);
        rs0 += __shfl_xor_sync(0xffffffffu, rs0, 2);
        rs1 += __shfl_xor_sync(0xffffffffu, rs1, 1);
        rs1 += __shfl_xor_sync(0xffffffffu, rs1, 2);

        l0 = l0 * a0 + rs0;  m0 = nm0;
        l1 = l1 * a1 + rs1;  m1 = nm1;

#pragma unroll
        for (int j = 0; j < 8; j++) {
            o[j][0] *= a0; o[j][1] *= a0;
            o[j][2] *= a1; o[j][3] *= a1;
        }

        // ---- O += P @ V (single fp16 P) ----
#pragma unroll
        for (int kk = 0; kk < 4; kk++) {
            uint32_t ph0 = pack_h2(s[2*kk][0],   s[2*kk][1]);
            uint32_t ph1 = pack_h2(s[2*kk][2],   s[2*kk][3]);
            uint32_t ph2 = pack_h2(s[2*kk+1][0], s[2*kk+1][1]);
            uint32_t ph3 = pack_h2(s[2*kk+1][2], s[2*kk+1][3]);
#pragma unroll
            for (int jp = 0; jp < 4; jp++) {
                int vrow = kk * 16 + (((lane >> 3) & 1) << 3) + (lane & 7);
                int vcol = jp * 16 + ((lane >> 4) << 3);
                uint32_t vd = stage + AT_TILE + (uint32_t)(vrow * AT_STRIDE + vcol) * 2;
                uint32_t v0, v1, v2, v3;
                ldmatrix_x4_trans(v0, v1, v2, v3, vd);
                mma_f16(o[jp*2][0],   o[jp*2][1],   o[jp*2][2],   o[jp*2][3],
                        ph0, ph1, ph2, ph3, v0, v1);
                mma_f16(o[jp*2+1][0], o[jp*2+1][1], o[jp*2+1][2], o[jp*2+1][3],
                        ph0, ph1, ph2, ph3, v2, v3);
            }
        }
        __syncthreads();
    }

    // ---- normalize + fp16 write for out-GEMM ----
    float inv0 = 1.f / l0, inv1 = 1.f / l1;
    const int orow = b * L_ + q0 + wid * 16 + (lane >> 2);
#pragma unroll
    for (int j = 0; j < 8; j++) {
        int col = basecol + j * 8 + (lane & 3) * 2;
        *(__half2*)(a16 + (size_t)orow * E_ + col) =
            __floats2half2_rn(o[j][0] * inv0, o[j][1] * inv0);
        *(__half2*)(a16 + (size_t)(orow + 8) * E_ + col) =
            __floats2half2_rn(o[j][2] * inv1, o[j][3] * inv1);
    }
}

// ---------------------------------------------------------------------------
extern "C" void kernel_launch(void* const* d_in, const int* in_sizes, int n_in,
                              void* d_out, int out_size)
{
    const float* x    = (const float*)d_in[0];
    const float* Wqkv = (const float*)d_in[1];
    const float* bqkv = (const float*)d_in[2];
    const float* Wout = (const float*)d_in[3];
    const float* bout = (const float*)d_in[4];
    float* out = (float*)d_out;

    __half *x16, *wq16, *wo16, *q16, *k16, *v16, *a16;
    cudaGetSymbolAddress((void**)&x16, g_x16);
    cudaGetSymbolAddress((void**)&wq16, g_wqkv16);
    cudaGetSymbolAddress((void**)&wo16, g_wo16);
    cudaGetSymbolAddress((void**)&q16, g_q16);
    cudaGetSymbolAddress((void**)&k16, g_k16);
    cudaGetSymbolAddress((void**)&v16, g_v16);
    cudaGetSymbolAddress((void**)&a16, g_a16);

    static int attr_done = 0;
    if (!attr_done) {
        cudaFuncSetAttribute((const void*)gemm_tc<0>,
                             cudaFuncAttributeMaxDynamicSharedMemorySize, GEMM_SMEM);
        cudaFuncSetAttribute((const void*)gemm_tc<1>,
                             cudaFuncAttributeMaxDynamicSharedMemorySize, GEMM_SMEM);
        cudaFuncSetAttribute(attention_tc,
                             cudaFuncAttributeMaxDynamicSharedMemorySize, ATTN_SMEM);
        attr_done = 1;
    }

    // 0) prepass: fp32 -> fp16
    conv_h<<<(M_ * E_ / 4 + 255) / 256, 256>>>(
        (const float4*)x, (__half2*)x16, M_ * E_ / 4);
    conv_h<<<(3 * E_ * E_ / 4 + 255) / 256, 256>>>(
        (const float4*)Wqkv, (__half2*)wq16, 3 * E_ * E_ / 4);
    conv_h<<<(E_ * E_ / 4 + 255) / 256, 256>>>(
        (const float4*)Wout, (__half2*)wo16, E_ * E_ / 4);

    // 1) QKV projection -> fp16 attention operands
    gemm_tc<1><<<dim3(3 * E_ / 128, M_ / 128), 256, GEMM_SMEM>>>(
        x16, wq16, bqkv, nullptr, q16, k16, v16, M_, 3 * E_, E_);

    // 2) attention -> fp16 attn output
    attention_tc<<<dim3(L_ / 128, H_, B_), 256, ATTN_SMEM>>>(
        q16, k16, v16, a16);

    // 3) out projection (fp32 epilogue)
    gemm_tc<0><<<dim3(E_ / 128, M_ / 128), 256, GEMM_SMEM>>>(
        a16, wo16, bout, out, nullptr, nullptr, nullptr, M_, E_, E_);
}

// round 13
// speedup vs baseline: 6.7588x; 1.0747x over previous
#include <cuda_runtime.h>
#include <cuda_bf16.h>
#include <cuda_fp16.h>
#include <math.h>
#include <stdint.h>

#define B_  2
#define L_  2048
#define E_  1024
#define H_  16
#define HD_ 64
#define M_  (B_ * L_)   // 4096

// ---------------------------------------------------------------------------
// Scratch (fp16 world)
// ---------------------------------------------------------------------------
__device__ __align__(16) __half g_x16[M_ * E_];       // x fp16
__device__ __align__(16) __half g_wqkv16[3 * E_ * E_];// Wqkv fp16
__device__ __align__(16) __half g_wo16[E_ * E_];      // Wout fp16
__device__ __align__(16) __half g_q16[M_ * E_];       // Q*0.125 fp16
__device__ __align__(16) __half g_k16[M_ * E_];       // K fp16
__device__ __align__(16) __half g_v16[M_ * E_];       // V fp16
__device__ __align__(16) __half g_a16[M_ * E_];       // attn out fp16

// ---------------------------------------------------------------------------
// helpers
// ---------------------------------------------------------------------------
__device__ __forceinline__ uint32_t smem_to_u32(const void* p) {
    uint32_t a;
    asm("{ .reg .u64 t; cvta.to.shared.u64 t, %1; cvt.u32.u64 %0, t; }" : "=r"(a) : "l"(p));
    return a;
}
__device__ __forceinline__ void cp_async16(uint32_t dst, const void* src) {
    asm volatile("cp.async.cg.shared.global [%0], [%1], 16;" :: "r"(dst), "l"(src));
}
#define CP_COMMIT() asm volatile("cp.async.commit_group;")
#define CP_WAIT1()  asm volatile("cp.async.wait_group 1;")
#define CP_WAIT0()  asm volatile("cp.async.wait_group 0;")

__device__ __forceinline__ void ldmatrix_x4(
    uint32_t& r0, uint32_t& r1, uint32_t& r2, uint32_t& r3, uint32_t addr)
{
    asm volatile("ldmatrix.sync.aligned.m8n8.x4.shared.b16 {%0,%1,%2,%3}, [%4];"
        : "=r"(r0), "=r"(r1), "=r"(r2), "=r"(r3) : "r"(addr));
}
__device__ __forceinline__ void ldmatrix_x4_trans(
    uint32_t& r0, uint32_t& r1, uint32_t& r2, uint32_t& r3, uint32_t addr)
{
    asm volatile("ldmatrix.sync.aligned.m8n8.x4.trans.shared.b16 {%0,%1,%2,%3}, [%4];"
        : "=r"(r0), "=r"(r1), "=r"(r2), "=r"(r3) : "r"(addr));
}
__device__ __forceinline__ void mma_f16(
    float& c0, float& c1, float& c2, float& c3,
    uint32_t a0, uint32_t a1, uint32_t a2, uint32_t a3, uint32_t b0, uint32_t b1)
{
    asm volatile(
        "mma.sync.aligned.m16n8k16.row.col.f32.f16.f16.f32 "
        "{%0,%1,%2,%3}, {%4,%5,%6,%7}, {%8,%9}, {%0,%1,%2,%3};"
        : "+f"(c0), "+f"(c1), "+f"(c2), "+f"(c3)
        : "r"(a0), "r"(a1), "r"(a2), "r"(a3), "r"(b0), "r"(b1));
}
__device__ __forceinline__ uint32_t pack_h2(float a, float b) {
    __half2 p = __floats2half2_rn(a, b);
    return *(uint32_t*)&p;
}

// ---------------------------------------------------------------------------
// Fused prepass: fp32 -> fp16 for x, Wqkv, Wout in one launch
// ---------------------------------------------------------------------------
#define NX4  (M_ * E_ / 4)           // 1048576
#define NWQ4 (3 * E_ * E_ / 4)       // 786432
#define NWO4 (E_ * E_ / 4)           // 262144
#define NALL4 (NX4 + NWQ4 + NWO4)

__global__ void conv_all(const float4* __restrict__ x,
                         const float4* __restrict__ wq,
                         const float4* __restrict__ wo,
                         __half2* __restrict__ x16,
                         __half2* __restrict__ wq16,
                         __half2* __restrict__ wo16)
{
    int i = blockIdx.x * blockDim.x + threadIdx.x;
    if (i >= NALL4) return;
    const float4* src;
    __half2* dst;
    int j;
    if (i < NX4)             { src = x;  dst = x16;  j = i; }
    else if (i < NX4 + NWQ4) { src = wq; dst = wq16; j = i - NX4; }
    else                     { src = wo; dst = wo16; j = i - NX4 - NWQ4; }
    float4 t = src[j];
    dst[2*j]   = __floats2half2_rn(t.x, t.y);
    dst[2*j+1] = __floats2half2_rn(t.z, t.w);
}

// ---------------------------------------------------------------------------
// GEMM: C = A16 @ W16^T (+bias), 1 fp16 MMA per atom. BK=32 (R10 config).
// BM=128, BN=128; 256 threads, 8 warps (warp tile 64x32).
// cp.async double-buffered, stride-40 rows.
// EPI=0: fp32+bias -> Cf. EPI=1: qkv epilogue -> fp16 attention operands.
// ---------------------------------------------------------------------------
#define GT_STRIDE 40
#define GT_TILE   (128 * GT_STRIDE * 2)   // 10240 B
#define GT_STAGE  (2 * GT_TILE)           // 20480 B (A, W)
#define GEMM_SMEM (2 * GT_STAGE)          // 40960 B

template<int EPI>
__global__ __launch_bounds__(256, 2) void gemm_tc(
    const __half* __restrict__ A16, const __half* __restrict__ W16,
    const float* __restrict__ bias, float* __restrict__ Cf,
    __half* __restrict__ q16, __half* __restrict__ k16, __half* __restrict__ v16,
    int M, int N, int K)
{
    extern __shared__ char smg[];
    const uint32_t sbase = smem_to_u32(smg);

    const int bm   = blockIdx.y * 128;
    const int bn   = blockIdx.x * 128;
    const int tid  = threadIdx.x;
    const int wid  = tid >> 5;
    const int lane = tid & 31;
    const int wm   = wid >> 2;
    const int wn   = wid & 3;

    float c[4][4][4];
#pragma unroll
    for (int i = 0; i < 4; i++)
#pragma unroll
        for (int j = 0; j < 4; j++)
#pragma unroll
            for (int r = 0; r < 4; r++) c[i][j][r] = 0.f;

    auto load_stage = [&](int s, int k0) {
        const uint32_t base = sbase + s * GT_STAGE;
        const __half* srcA = A16 + (size_t)bm * K + k0;
        const __half* srcW = W16 + (size_t)bn * K + k0;
        // per tile: 128 rows x 4 chunks(16B) = 512 chunks; 2 per thread per tile
#pragma unroll
        for (int i = 0; i < 2; i++) {
            int chunk = tid * 2 + i;
            int row   = chunk >> 2;
            int cc    = chunk & 3;
            uint32_t doff = row * (GT_STRIDE * 2) + cc * 16;
            cp_async16(base + doff,           srcA + (size_t)row * K + cc * 8);
            cp_async16(base + GT_TILE + doff, srcW + (size_t)row * K + cc * 8);
        }
    };

    load_stage(0, 0);
    CP_COMMIT();

    const int niter = K / 32;
    for (int it = 0; it < niter; it++) {
        if (it + 1 < niter) { load_stage((it + 1) & 1, (it + 1) * 32); CP_COMMIT(); CP_WAIT1(); }
        else                { CP_WAIT0(); }
        __syncthreads();

        const uint32_t stage = sbase + (it & 1) * GT_STAGE;
#pragma unroll
        for (int ks = 0; ks < 2; ks++) {
            const int kof = ks * 16;
            uint32_t af[4][4], bfr[4][2];
#pragma unroll
            for (int i = 0; i < 4; i++) {
                int m0 = wm * 64 + i * 16;
                uint32_t ad = stage +
                    (uint32_t)((m0 + (lane & 15)) * GT_STRIDE + kof + (lane >> 4) * 8) * 2;
                ldmatrix_x4(af[i][0], af[i][1], af[i][2], af[i][3], ad);
            }
#pragma unroll
            for (int jp = 0; jp < 2; jp++) {
                int n0 = wn * 32 + jp * 16;
                int nrow = n0 + ((lane >> 4) << 3) + (lane & 7);
                int bk   = kof + (((lane >> 3) & 1) << 3);
                uint32_t bd = stage + GT_TILE + (uint32_t)(nrow * GT_STRIDE + bk) * 2;
                ldmatrix_x4(bfr[jp*2][0], bfr[jp*2][1], bfr[jp*2+1][0], bfr[jp*2+1][1], bd);
            }
#pragma unroll
            for (int i = 0; i < 4; i++)
#pragma unroll
                for (int j = 0; j < 4; j++)
                    mma_f16(c[i][j][0], c[i][j][1], c[i][j][2], c[i][j][3],
                            af[i][0], af[i][1], af[i][2], af[i][3],
                            bfr[j][0], bfr[j][1]);
        }
        __syncthreads();
    }

    // ---- epilogue ----
    const int g4 = lane >> 2;
    const int t4 = lane & 3;
    if (EPI == 0) {
#pragma unroll
        for (int i = 0; i < 4; i++) {
            int row0 = bm + wm * 64 + i * 16 + g4;
#pragma unroll
            for (int j = 0; j < 4; j++) {
                int col = bn + wn * 32 + j * 8 + t4 * 2;
                float bx = bias[col], by = bias[col + 1];
                *(float2*)(Cf + (size_t)row0 * N + col) =
                    make_float2(c[i][j][0] + bx, c[i][j][1] + by);
                *(float2*)(Cf + (size_t)(row0 + 8) * N + col) =
                    make_float2(c[i][j][2] + bx, c[i][j][3] + by);
            }
        }
    } else {
        const int seg     = bn >> 10;          // 0=Q, 1=K, 2=V
        const int segbase = bn & 1023;
#pragma unroll
        for (int i = 0; i < 4; i++) {
            int row0 = bm + wm * 64 + i * 16 + g4;
#pragma unroll
            for (int j = 0; j < 4; j++) {
                int colg = bn + wn * 32 + j * 8 + t4 * 2;
                int cols = segbase + wn * 32 + j * 8 + t4 * 2;
                float bx = bias[colg], by = bias[colg + 1];
                float v0 = c[i][j][0] + bx, v1 = c[i][j][1] + by;
                float v2 = c[i][j][2] + bx, v3 = c[i][j][3] + by;
                size_t i0 = (size_t)row0 * E_ + cols;
                size_t i1 = (size_t)(row0 + 8) * E_ + cols;
                if (seg == 0) {
                    *(__half2*)(q16 + i0) = __floats2half2_rn(v0 * 0.125f, v1 * 0.125f);
                    *(__half2*)(q16 + i1) = __floats2half2_rn(v2 * 0.125f, v3 * 0.125f);
                } else if (seg == 1) {
                    *(__half2*)(k16 + i0) = __floats2half2_rn(v0, v1);
                    *(__half2*)(k16 + i1) = __floats2half2_rn(v2, v3);
                } else {
                    *(__half2*)(v16 + i0) = __floats2half2_rn(v0, v1);
                    *(__half2*)(v16 + i1) = __floats2half2_rn(v2, v3);
                }
            }
        }
    }
}

// ---------------------------------------------------------------------------
// Flash attention: S = Q16 @ K16^T (1 mma); O += P16 @ V16 (1 mma).
// Block: (b, h, 128 q-rows). K-tiles of 64. cp.async double buffer.
// 2 CTAs/SM target.
// ---------------------------------------------------------------------------
#define AT_STRIDE 72
#define AT_TILE   (64 * AT_STRIDE * 2)     // 9216
#define AT_STAGE  (2 * AT_TILE)            // 18432 (K16, V16)
#define ATTN_SMEM (2 * AT_STAGE)           // 36864

__global__ __launch_bounds__(256, 2) void attention_tc(
    const __half* __restrict__ q16,
    const __half* __restrict__ k16, const __half* __restrict__ v16,
    __half* __restrict__ a16)
{
    extern __shared__ char sma[];
    const uint32_t sbase = smem_to_u32(sma);

    const int q0   = blockIdx.x * 128;
    const int h    = blockIdx.y;
    const int b    = blockIdx.z;
    const int tid  = threadIdx.x;
    const int wid  = tid >> 5;
    const int lane = tid & 31;
    const int basecol = h * HD_;

    // ---- Q fragments directly from global (ldmatrix A-frag layout) ----
    uint32_t qf[4][4];
    {
        const int r0 = b * L_ + q0 + wid * 16 + (lane >> 2);
        const int c0 = basecol + (lane & 3) * 2;
#pragma unroll
        for (int ks = 0; ks < 4; ks++) {
            size_t i00 = (size_t)r0 * E_ + c0 + ks * 16;
            qf[ks][0] = *(const uint32_t*)(q16 + i00);
            qf[ks][1] = *(const uint32_t*)(q16 + i00 + 8 * E_);
            qf[ks][2] = *(const uint32_t*)(q16 + i00 + 8);
            qf[ks][3] = *(const uint32_t*)(q16 + i00 + 8 * E_ + 8);
        }
    }

    auto load_kv = [&](int s, int kt) {
        const uint32_t base = sbase + s * AT_STAGE;
        const int rowg = b * L_ + kt;
#pragma unroll
        for (int i = 0; i < 2; i++) {
            int chunk = tid * 2 + i;        // 0..511
            int row   = chunk >> 3;
            int cc    = chunk & 7;
            size_t src = (size_t)(rowg + row) * E_ + basecol + cc * 8;
            uint32_t doff = row * (AT_STRIDE * 2) + cc * 16;
            cp_async16(base + doff,           k16 + src);
            cp_async16(base + AT_TILE + doff, v16 + src);
        }
    };

    load_kv(0, 0);
    CP_COMMIT();

    float o[8][4];
#pragma unroll
    for (int j = 0; j < 8; j++)
#pragma unroll
        for (int r = 0; r < 4; r++) o[j][r] = 0.f;
    float m0 = -1e30f, m1 = -1e30f, l0 = 0.f, l1 = 0.f;

    const int NTILE = L_ / 64;
    for (int it = 0; it < NTILE; it++) {
        if (it + 1 < NTILE) { load_kv((it + 1) & 1, (it + 1) * 64); CP_COMMIT(); CP_WAIT1(); }
        else                { CP_WAIT0(); }
        __syncthreads();

        const uint32_t stage = sbase + (it & 1) * AT_STAGE;

        // ---- S = Q @ K^T, fp16 ----
        float s[8][4];
#pragma unroll
        for (int j = 0; j < 8; j++)
#pragma unroll
            for (int r = 0; r < 4; r++) s[j][r] = 0.f;

#pragma unroll
        for (int ks = 0; ks < 4; ks++) {
            const int kof = ks * 16;
            uint32_t kf[8][2];
#pragma unroll
            for (int jp = 0; jp < 4; jp++) {
                int nrow = jp * 16 + ((lane >> 4) << 3) + (lane & 7);
                int bk   = kof + (((lane >> 3) & 1) << 3);
                uint32_t bd = stage + (uint32_t)(nrow * AT_STRIDE + bk) * 2;
                ldmatrix_x4(kf[jp*2][0], kf[jp*2][1], kf[jp*2+1][0], kf[jp*2+1][1], bd);
            }
#pragma unroll
            for (int j = 0; j < 8; j++)
                mma_f16(s[j][0], s[j][1], s[j][2], s[j][3],
                        qf[ks][0], qf[ks][1], qf[ks][2], qf[ks][3],
                        kf[j][0], kf[j][1]);
        }

        // ---- online softmax ----
        float rm0 = -1e30f, rm1 = -1e30f;
#pragma unroll
        for (int j = 0; j < 8; j++) {
            rm0 = fmaxf(rm0, fmaxf(s[j][0], s[j][1]));
            rm1 = fmaxf(rm1, fmaxf(s[j][2], s[j][3]));
        }
        rm0 = fmaxf(rm0, __shfl_xor_sync(0xffffffffu, rm0, 1));
        rm0 = fmaxf(rm0, __shfl_xor_sync(0xffffffffu, rm0, 2));
        rm1 = fmaxf(rm1, __shfl_xor_sync(0xffffffffu, rm1, 1));
        rm1 = fmaxf(rm1, __shfl_xor_sync(0xffffffffu, rm1, 2));

        float nm0 = fmaxf(m0, rm0), nm1 = fmaxf(m1, rm1);
        float a0 = __expf(m0 - nm0), a1 = __expf(m1 - nm1);

        float rs0 = 0.f, rs1 = 0.f;
#pragma unroll
        for (int j = 0; j < 8; j++) {
            s[j][0] = __expf(s[j][0] - nm0);
            s[j][1] = __expf(s[j][1] - nm0);
            s[j][2] = __expf(s[j][2] - nm1);
            s[j][3] = __expf(s[j][3] - nm1);
            rs0 += s[j][0] + s[j][1];
            rs1 += s[j][2] + s[j][3];
        }
        rs0 += __shfl_xor_sync(0xffffffffu, rs0, 1);
        rs0 += __shfl_xor_sync(0xffffffffu, rs0, 2);
        rs1 += __shfl_xor_sync(0xffffffffu, rs1, 1);
        rs1 += __shfl_xor_sync(0xffffffffu, rs1, 2);

        l0 = l0 * a0 + rs0;  m0 = nm0;
        l1 = l1 * a1 + rs1;  m1 = nm1;

#pragma unroll
        for (int j = 0; j < 8; j++) {
            o[j][0] *= a0; o[j][1] *= a0;
            o[j][2] *= a1; o[j][3] *= a1;
        }

        // ---- O += P @ V (single fp16 P) ----
#pragma unroll
        for (int kk = 0; kk < 4; kk++) {
            uint32_t ph0 = pack_h2(s[2*kk][0],   s[2*kk][1]);
            uint32_t ph1 = pack_h2(s[2*kk][2],   s[2*kk][3]);
            uint32_t ph2 = pack_h2(s[2*kk+1][0], s[2*kk+1][1]);
            uint32_t ph3 = pack_h2(s[2*kk+1][2], s[2*kk+1][3]);
#pragma unroll
            for (int jp = 0; jp < 4; jp++) {
                int vrow = kk * 16 + (((lane >> 3) & 1) << 3) + (lane & 7);
                int vcol = jp * 16 + ((lane >> 4) << 3);
                uint32_t vd = stage + AT_TILE + (uint32_t)(vrow * AT_STRIDE + vcol) * 2;
                uint32_t v0, v1, v2, v3;
                ldmatrix_x4_trans(v0, v1, v2, v3, vd);
                mma_f16(o[jp*2][0],   o[jp*2][1],   o[jp*2][2],   o[jp*2][3],
                        ph0, ph1, ph2, ph3, v0, v1);
                mma_f16(o[jp*2+1][0], o[jp*2+1][1], o[jp*2+1][2], o[jp*2+1][3],
                        ph0, ph1, ph2, ph3, v2, v3);
            }
        }
        __syncthreads();
    }

    // ---- normalize + fp16 write for out-GEMM ----
    float inv0 = 1.f / l0, inv1 = 1.f / l1;
    const int orow = b * L_ + q0 + wid * 16 + (lane >> 2);
#pragma unroll
    for (int j = 0; j < 8; j++) {
        int col = basecol + j * 8 + (lane & 3) * 2;
        *(__half2*)(a16 + (size_t)orow * E_ + col) =
            __floats2half2_rn(o[j][0] * inv0, o[j][1] * inv0);
        *(__half2*)(a16 + (size_t)(orow + 8) * E_ + col) =
            __floats2half2_rn(o[j][2] * inv1, o[j][3] * inv1);
    }
}

// ---------------------------------------------------------------------------
extern "C" void kernel_launch(void* const* d_in, const int* in_sizes, int n_in,
                              void* d_out, int out_size)
{
    const float* x    = (const float*)d_in[0];
    const float* Wqkv = (const float*)d_in[1];
    const float* bqkv = (const float*)d_in[2];
    const float* Wout = (const float*)d_in[3];
    const float* bout = (const float*)d_in[4];
    float* out = (float*)d_out;

    __half *x16, *wq16, *wo16, *q16, *k16, *v16, *a16;
    cudaGetSymbolAddress((void**)&x16, g_x16);
    cudaGetSymbolAddress((void**)&wq16, g_wqkv16);
    cudaGetSymbolAddress((void**)&wo16, g_wo16);
    cudaGetSymbolAddress((void**)&q16, g_q16);
    cudaGetSymbolAddress((void**)&k16, g_k16);
    cudaGetSymbolAddress((void**)&v16, g_v16);
    cudaGetSymbolAddress((void**)&a16, g_a16);

    static int attr_done = 0;
    if (!attr_done) {
        cudaFuncSetAttribute((const void*)gemm_tc<0>,
                             cudaFuncAttributeMaxDynamicSharedMemorySize, GEMM_SMEM);
        cudaFuncSetAttribute((const void*)gemm_tc<1>,
                             cudaFuncAttributeMaxDynamicSharedMemorySize, GEMM_SMEM);
        cudaFuncSetAttribute(attention_tc,
                             cudaFuncAttributeMaxDynamicSharedMemorySize, ATTN_SMEM);
        attr_done = 1;
    }

    // 0) fused prepass: fp32 -> fp16 (x, Wqkv, Wout)
    conv_all<<<(NALL4 + 255) / 256, 256>>>(
        (const float4*)x, (const float4*)Wqkv, (const float4*)Wout,
        (__half2*)x16, (__half2*)wq16, (__half2*)wo16);

    // 1) QKV projection -> fp16 attention operands
    gemm_tc<1><<<dim3(3 * E_ / 128, M_ / 128), 256, GEMM_SMEM>>>(
        x16, wq16, bqkv, nullptr, q16, k16, v16, M_, 3 * E_, E_);

    // 2) attention -> fp16 attn output
    attention_tc<<<dim3(L_ / 128, H_, B_), 256, ATTN_SMEM>>>(
        q16, k16, v16, a16);

    // 3) out projection (fp32 epilogue)
    gemm_tc<0><<<dim3(E_ / 128, M_ / 128), 256, GEMM_SMEM>>>(
        a16, wo16, bout, out, nullptr, nullptr, nullptr, M_, E_, E_);
}